// round 11
// baseline (speedup 1.0000x reference)
#include <cuda_runtime.h>
#include <math.h>
#include <stddef.h>

// ---------------- problem constants ----------------
#define SQv   2048
#define Dv    1024
#define Hv    16
#define DHv   64
#define NCv   4096
#define LTv   16
#define KHv   8
#define LKv   128
#define NBv   256
#define TPPv  1024
#define SSv   1024
#define PPv   64
#define NTOK  2048

// ---------------- device scratch ----------------
__device__ __align__(16) float    g_xln   [SQv*Dv];
__device__ __align__(16) unsigned g_qh    [SQv*Dv];
__device__ __align__(16) unsigned g_ql    [SQv*Dv];
__device__ __align__(16) unsigned g_kh    [SQv*Dv];
__device__ __align__(16) unsigned g_kl    [SQv*Dv];
__device__ __align__(16) float    g_v     [SQv*Dv];
__device__ __align__(16) unsigned g_vth   [Dv*SQv];
__device__ __align__(16) unsigned g_vtl   [Dv*SQv];
__device__ __align__(16) float    g_ctx   [SQv*Dv];
__device__ __align__(16) float    g_attn  [SQv*Dv];
__device__ __align__(16) float    g_normed[SQv*Dv];
__device__ __align__(16) float    g_msk   [SQv];
__device__ __align__(16) float    g_projn [LKv*NCv];
__device__ __align__(16) float    g_projt [LKv*NTOK];
__device__ __align__(16) float    g_tanhpt[NTOK*LKv];
__device__ __align__(16) float    g_tanhpns[2*SSv*LKv];
__device__ __align__(16) float    g_w1s   [2*SSv*Dv];
__device__ __align__(16) float    g_w2sT  [2*(size_t)Dv*SSv];
__device__ __align__(16) float    g_b1s   [2*SSv];
__device__ __align__(16) float    g_logits[NTOK*SSv];
__device__ __align__(16) float    g_acts  [NTOK*SSv];
__device__ __align__(16) float    g_trip  [NTOK];
__device__ int g_coden[LTv*NCv];
__device__ int g_hist [2*LTv*NBv];
__device__ int g_score[2*NCv];
__device__ int g_sids [2*SSv];

// ---------------- helpers ----------------
__device__ __forceinline__ unsigned f2tf(float x){
    unsigned u; asm("cvt.rna.tf32.f32 %0, %1;" : "=r"(u) : "f"(x)); return u;
}
__device__ __forceinline__ void mma8(float* d, const unsigned* a, const unsigned* b){
    asm volatile("mma.sync.aligned.m16n8k8.row.col.f32.tf32.tf32.f32 "
        "{%0,%1,%2,%3},{%4,%5,%6,%7},{%8,%9},{%0,%1,%2,%3};"
        : "+f"(d[0]), "+f"(d[1]), "+f"(d[2]), "+f"(d[3])
        : "r"(a[0]), "r"(a[1]), "r"(a[2]), "r"(a[3]), "r"(b[0]), "r"(b[1]));
}
__device__ __forceinline__ float gelu_exact(float x){
    return 0.5f * x * (1.f + erff(x * 0.70710678118654752f));
}
__device__ __forceinline__ unsigned s2u(const void* p){
    return (unsigned)__cvta_generic_to_shared(p);
}
__device__ __forceinline__ void cpa16(unsigned dst, const void* src){
    asm volatile("cp.async.ca.shared.global [%0], [%1], 16;" :: "r"(dst), "l"(src));
}
__device__ __forceinline__ void cpa_commit(){ asm volatile("cp.async.commit_group;"); }
__device__ __forceinline__ void cpa_wait0(){ asm volatile("cp.async.wait_group 0;" ::: "memory"); }
// permute column-within-8 so fragment pairs (s, s+4) are adjacent
__device__ __forceinline__ int pc8(int c){
    int s = c & 7; return (c & ~7) | (2*(s&3) + (s>>2));
}

// ---------------- LayerNorm ----------------
__global__ void ln_kernel(const float* __restrict__ x, const float* __restrict__ g,
                          const float* __restrict__ b, float* __restrict__ y)
{
    int row = blockIdx.x;
    const float* xr = x + (size_t)row * Dv;
    __shared__ float red[256];
    int tid = threadIdx.x;
    float s = 0.f, ss = 0.f;
    for (int i = tid; i < Dv; i += 256) { float v = xr[i]; s += v; ss += v * v; }
    red[tid] = s; __syncthreads();
    for (int st = 128; st > 0; st >>= 1) { if (tid < st) red[tid] += red[tid + st]; __syncthreads(); }
    float mean = red[0] / Dv;
    __syncthreads();
    red[tid] = ss; __syncthreads();
    for (int st = 128; st > 0; st >>= 1) { if (tid < st) red[tid] += red[tid + st]; __syncthreads(); }
    float var = red[0] / Dv - mean * mean;
    float inv = rsqrtf(var + 1e-12f);
    float* yr = y + (size_t)row * Dv;
    for (int i = tid; i < Dv; i += 256) yr[i] = (xr[i] - mean) * inv * g[i] + b[i];
}

__global__ void msk_kernel(const float* __restrict__ mask)
{
    int i = blockIdx.x * 256 + threadIdx.x;
    if (i < SQv) g_msk[i] = -1000.f * (1.f - mask[i]);
}

// ---------------- TF32 tensor-core GEMM NT ----------------
// EPI=0: C fp32. EPI=1: C fp32 + gelu(C)->C2. EPI=3: split hi->C lo->C2 with pc8 column permute.
// CHSEL: per-M-chunk B/bias select (chunk = row block >= TPPv), B stride fixed 2^20, bias stride BIASZ.
template<int SPLIT, int EPI, bool BIAS, bool RES, int BM_, int BN_, bool CHSEL, int BIASZ>
__global__ void __launch_bounds__(256, 1)
mma_nt(const float* __restrict__ A, const float* __restrict__ B,
       const float* __restrict__ bias, const float* __restrict__ res,
       float* __restrict__ C, float* __restrict__ C2, int M, int N, int K)
{
    constexpr int BK = 32, LD = 36;
    constexpr int WTM = BM_ / 2, WTN = BN_ / 4;
    constexpr int MT = WTM / 16, NT = WTN / 8;
    extern __shared__ unsigned sm[];
    unsigned* Ah = sm;
    unsigned* Bh = Ah + BM_ * LD;
    unsigned* Al = (SPLIT == 3) ? Bh + BN_ * LD : Ah;
    unsigned* Bl = (SPLIT == 3) ? Al + BM_ * LD : Bh;

    if (CHSEL) {
        if ((int)(blockIdx.y * BM_) >= TPPv) {
            B += (size_t)SSv * Dv;
            bias += BIASZ;
        }
    }

    const int tid = threadIdx.x;
    const int lane = tid & 31, wid = tid >> 5;
    const int wm = wid & 1, wn = wid >> 1;
    const int m0 = blockIdx.y * BM_, n0 = blockIdx.x * BN_;

    constexpr int PA = BM_ / 32;
    constexpr int PB = BN_ / 32;
    const int lrw = tid >> 3;
    const int lcc = (tid & 7) * 4;

    float4 pa[PA], pb[PB];
    float acc[MT][NT][4];
    #pragma unroll
    for (int i = 0; i < MT; i++)
        #pragma unroll
        for (int j = 0; j < NT; j++)
            #pragma unroll
            for (int u = 0; u < 4; u++) acc[i][j][u] = 0.f;

    #pragma unroll
    for (int p = 0; p < PA; p++)
        pa[p] = *(const float4*)(A + (size_t)(m0 + p*32 + lrw) * K + lcc);
    #pragma unroll
    for (int p = 0; p < PB; p++)
        pb[p] = *(const float4*)(B + (size_t)(n0 + p*32 + lrw) * K + lcc);

    const int ntiles = K / BK;
    for (int kt = 0; kt < ntiles; kt++) {
        __syncthreads();
        #pragma unroll
        for (int p = 0; p < PA; p++) {
            float vv[4] = {pa[p].x, pa[p].y, pa[p].z, pa[p].w};
            #pragma unroll
            for (int i = 0; i < 4; i++) {
                unsigned h = f2tf(vv[i]);
                Ah[(p*32 + lrw) * LD + lcc + i] = h;
                if (SPLIT == 3)
                    Al[(p*32 + lrw) * LD + lcc + i] = f2tf(vv[i] - __uint_as_float(h));
            }
        }
        #pragma unroll
        for (int p = 0; p < PB; p++) {
            float vv[4] = {pb[p].x, pb[p].y, pb[p].z, pb[p].w};
            #pragma unroll
            for (int i = 0; i < 4; i++) {
                unsigned h = f2tf(vv[i]);
                Bh[(p*32 + lrw) * LD + lcc + i] = h;
                if (SPLIT == 3)
                    Bl[(p*32 + lrw) * LD + lcc + i] = f2tf(vv[i] - __uint_as_float(h));
            }
        }
        __syncthreads();
        if (kt + 1 < ntiles) {
            const float* An = A + (size_t)(kt + 1) * BK;
            const float* Bn = B + (size_t)(kt + 1) * BK;
            #pragma unroll
            for (int p = 0; p < PA; p++)
                pa[p] = *(const float4*)(An + (size_t)(m0 + p*32 + lrw) * K + lcc);
            #pragma unroll
            for (int p = 0; p < PB; p++)
                pb[p] = *(const float4*)(Bn + (size_t)(n0 + p*32 + lrw) * K + lcc);
        }
        #pragma unroll
        for (int ks = 0; ks < 4; ks++) {
            unsigned ah[MT][4], al[MT][4], bh[NT][2], bl[NT][2];
            #pragma unroll
            for (int i = 0; i < MT; i++) {
                int r = wm * WTM + i * 16 + (lane >> 2);
                int c = ks * 8 + (lane & 3);
                ah[i][0] = Ah[r*LD + c];       ah[i][1] = Ah[(r+8)*LD + c];
                ah[i][2] = Ah[r*LD + c + 4];   ah[i][3] = Ah[(r+8)*LD + c + 4];
                if (SPLIT == 3) {
                    al[i][0] = Al[r*LD + c];     al[i][1] = Al[(r+8)*LD + c];
                    al[i][2] = Al[r*LD + c + 4]; al[i][3] = Al[(r+8)*LD + c + 4];
                }
            }
            #pragma unroll
            for (int j = 0; j < NT; j++) {
                int r = wn * WTN + j * 8 + (lane >> 2);
                int c = ks * 8 + (lane & 3);
                bh[j][0] = Bh[r*LD + c];  bh[j][1] = Bh[r*LD + c + 4];
                if (SPLIT == 3) {
                    bl[j][0] = Bl[r*LD + c];  bl[j][1] = Bl[r*LD + c + 4];
                }
            }
            #pragma unroll
            for (int i = 0; i < MT; i++)
                #pragma unroll
                for (int j = 0; j < NT; j++) {
                    mma8(acc[i][j], ah[i], bh[j]);
                    if (SPLIT == 3) {
                        mma8(acc[i][j], ah[i], bl[j]);
                        mma8(acc[i][j], al[i], bh[j]);
                    }
                }
        }
    }
    #pragma unroll
    for (int i = 0; i < MT; i++) {
        #pragma unroll
        for (int j = 0; j < NT; j++) {
            int r = m0 + wm * WTM + i * 16 + (lane >> 2);
            int c = n0 + wn * WTN + j * 8 + (lane & 3) * 2;
            float v00 = acc[i][j][0], v01 = acc[i][j][1];
            float v10 = acc[i][j][2], v11 = acc[i][j][3];
            if (BIAS) { float b0 = bias[c], b1 = bias[c+1]; v00 += b0; v01 += b1; v10 += b0; v11 += b1; }
            if (RES) {
                v00 += res[(size_t)r*N + c];     v01 += res[(size_t)r*N + c + 1];
                v10 += res[(size_t)(r+8)*N + c]; v11 += res[(size_t)(r+8)*N + c + 1];
            }
            if (EPI == 3) {
                unsigned* Chi = (unsigned*)C;
                unsigned* Clo = (unsigned*)C2;
                int cp0 = pc8(c), cp1 = pc8(c + 1);
                unsigned h00 = f2tf(v00), h01 = f2tf(v01), h10 = f2tf(v10), h11 = f2tf(v11);
                Chi[(size_t)r*N + cp0]     = h00;  Chi[(size_t)r*N + cp1]     = h01;
                Chi[(size_t)(r+8)*N + cp0] = h10;  Chi[(size_t)(r+8)*N + cp1] = h11;
                Clo[(size_t)r*N + cp0]     = f2tf(v00 - __uint_as_float(h00));
                Clo[(size_t)r*N + cp1]     = f2tf(v01 - __uint_as_float(h01));
                Clo[(size_t)(r+8)*N + cp0] = f2tf(v10 - __uint_as_float(h10));
                Clo[(size_t)(r+8)*N + cp1] = f2tf(v11 - __uint_as_float(h11));
            } else {
                *(float2*)(C + (size_t)r*N + c)     = make_float2(v00, v01);
                *(float2*)(C + (size_t)(r+8)*N + c) = make_float2(v10, v11);
                if (EPI == 1) {
                    *(float2*)(C2 + (size_t)r*N + c)     = make_float2(gelu_exact(v00), gelu_exact(v01));
                    *(float2*)(C2 + (size_t)(r+8)*N + c) = make_float2(gelu_exact(v10), gelu_exact(v11));
                }
            }
        }
    }
}

// ---------------- exact-fp32 GEMM NT (hash projections) ----------------
// TANHT: also write tanh(C) transposed into g_tanhpt[t][lk]
template<bool HAS_BIAS, bool TANHT>
__global__ void gemm_nt(const float* __restrict__ A, const float* __restrict__ Bm,
                        const float* __restrict__ bias,
                        float* __restrict__ C, int M, int N, int Kd)
{
    __shared__ float As[16][64];
    __shared__ float Bs[16][64];
    int tid = threadIdx.x;
    int tx = tid & 15, ty = tid >> 4;
    int m0 = blockIdx.y * 64, n0 = blockIdx.x * 64;
    float acc[4][4] = {};
    for (int k0 = 0; k0 < Kd; k0 += 16) {
        int idx = tid * 4;
        int r = idx >> 4, kk = idx & 15;
        float4 av = *(const float4*)(A  + (size_t)(m0 + r) * Kd + k0 + kk);
        As[kk+0][r] = av.x; As[kk+1][r] = av.y; As[kk+2][r] = av.z; As[kk+3][r] = av.w;
        float4 bv = *(const float4*)(Bm + (size_t)(n0 + r) * Kd + k0 + kk);
        Bs[kk+0][r] = bv.x; Bs[kk+1][r] = bv.y; Bs[kk+2][r] = bv.z; Bs[kk+3][r] = bv.w;
        __syncthreads();
        #pragma unroll
        for (int q = 0; q < 16; q++) {
            float a[4], b[4];
            #pragma unroll
            for (int i = 0; i < 4; i++) a[i] = As[q][ty*4+i];
            #pragma unroll
            for (int j = 0; j < 4; j++) b[j] = Bs[q][tx*4+j];
            #pragma unroll
            for (int i = 0; i < 4; i++)
                #pragma unroll
                for (int j = 0; j < 4; j++)
                    acc[i][j] += a[i] * b[j];
        }
        __syncthreads();
    }
    #pragma unroll
    for (int i = 0; i < 4; i++) {
        int m = m0 + ty*4 + i;
        #pragma unroll
        for (int j = 0; j < 4; j++) {
            int n = n0 + tx*4 + j;
            float v = acc[i][j];
            if (HAS_BIAS) v += bias[n];
            C[(size_t)m * N + n] = v;
            if (TANHT) g_tanhpt[(size_t)n * LKv + m] = tanhf(v);
        }
    }
}

// ---------------- V transpose + split + key-permute: g_v -> g_vth/g_vtl [Dv][SQv] ----------------
__global__ void vtrans_kernel(const float* __restrict__ v)
{
    __shared__ float t[32][33];
    int k0 = blockIdx.x * 32, d0 = blockIdx.y * 32;
    int tx = threadIdx.x & 31, ty = threadIdx.x >> 5;
    for (int r = ty; r < 32; r += 8)
        t[r][tx] = v[(size_t)(k0 + r) * Dv + d0 + tx];
    __syncthreads();
    int key = k0 + tx;
    int kp = pc8(key);
    for (int r = ty; r < 32; r += 8) {
        float val = t[tx][r];
        unsigned hi = f2tf(val);
        g_vth[(size_t)(d0 + r) * SQv + kp] = hi;
        g_vtl[(size_t)(d0 + r) * SQv + kp] = f2tf(val - __uint_as_float(hi));
    }
}

// ---------------- attention: 3xTF32 flash, permuted fragments, shuffle-P ----------------
#define LDA 72
__global__ void __launch_bounds__(128, 3)
attn5(const unsigned* __restrict__ qh_g, const unsigned* __restrict__ ql_g,
      const unsigned* __restrict__ kh_g, const unsigned* __restrict__ kl_g,
      const unsigned* __restrict__ vth_g, const unsigned* __restrict__ vtl_g,
      float* __restrict__ ctx)
{
    extern __shared__ unsigned sm[];
    unsigned* Kh = sm;                  // [key][d-perm]
    unsigned* Kl = Kh + 64*LDA;
    unsigned* Vh = Kl + 64*LDA;         // [d][key-perm]
    unsigned* Vl = Vh + 64*LDA;
    float*    Ms = (float*)(Vl + 64*LDA);

    const int tid = threadIdx.x;
    const int lane = tid & 31, w = tid >> 5;
    const int lq = lane & 3, ln4 = lane >> 2;
    const int h = blockIdx.y, q0 = blockIdx.x * 64;
    const int rr = w * 16 + ln4;

    const unsigned uKh = s2u(Kh), uKl = s2u(Kl), uVh = s2u(Vh), uVl = s2u(Vl);
    const unsigned uMs = s2u(Ms);

    // preload Q (d-permuted layout) into K buffers
    #pragma unroll
    for (int p = 0; p < 8; p++) {
        int idx = tid + p * 128;
        int row = idx >> 4, c4 = (idx & 15) * 4;
        size_t gof = (size_t)(q0 + row) * Dv + h * 64 + c4;
        unsigned sof = (row * LDA + c4) * 4;
        cpa16(uKh + sof, qh_g + gof);
        cpa16(uKl + sof, ql_g + gof);
    }
    cpa_commit(); cpa_wait0();
    __syncthreads();

    unsigned qh[8][4], ql[8][4];
    #pragma unroll
    for (int ks = 0; ks < 8; ks++) {
        uint2 t0 = *(uint2*)&Kh[rr*LDA + 8*ks + 2*lq];
        uint2 t1 = *(uint2*)&Kh[(rr+8)*LDA + 8*ks + 2*lq];
        qh[ks][0] = t0.x; qh[ks][2] = t0.y; qh[ks][1] = t1.x; qh[ks][3] = t1.y;
        uint2 u0 = *(uint2*)&Kl[rr*LDA + 8*ks + 2*lq];
        uint2 u1 = *(uint2*)&Kl[(rr+8)*LDA + 8*ks + 2*lq];
        ql[ks][0] = u0.x; ql[ks][2] = u0.y; ql[ks][1] = u1.x; ql[ks][3] = u1.y;
    }

    float o[8][4];
    #pragma unroll
    for (int j = 0; j < 8; j++)
        #pragma unroll
        for (int u = 0; u < 4; u++) o[j][u] = 0.f;
    float m0r = -1e30f, m1r = -1e30f, l0 = 0.f, l1 = 0.f;

    for (int kt = 0; kt < SQv / 64; kt++) {
        int k0 = kt * 64;
        __syncthreads();
        #pragma unroll
        for (int p = 0; p < 8; p++) {
            int idx = tid + p * 128;
            int row = idx >> 4, c4 = (idx & 15) * 4;
            unsigned sof = (row * LDA + c4) * 4;
            size_t gK = (size_t)(k0 + row) * Dv + h * 64 + c4;
            size_t gV = (size_t)(h * 64 + row) * SQv + k0 + c4;
            cpa16(uKh + sof, kh_g + gK);
            cpa16(uKl + sof, kl_g + gK);
            cpa16(uVh + sof, vth_g + gV);
            cpa16(uVl + sof, vtl_g + gV);
        }
        if (tid < 16) cpa16(uMs + tid * 16, g_msk + k0 + tid * 4);
        cpa_commit(); cpa_wait0();
        __syncthreads();

        // S = Q K^T (3x split), LDS.64 B fragments
        float s[8][4];
        #pragma unroll
        for (int j = 0; j < 8; j++)
            #pragma unroll
            for (int u = 0; u < 4; u++) s[j][u] = 0.f;
        #pragma unroll
        for (int ks = 0; ks < 8; ks++) {
            #pragma unroll
            for (int j = 0; j < 8; j++) {
                int r = j * 8 + ln4;
                uint2 b2h = *(uint2*)&Kh[r*LDA + 8*ks + 2*lq];
                uint2 b2l = *(uint2*)&Kl[r*LDA + 8*ks + 2*lq];
                unsigned bh[2] = {b2h.x, b2h.y};
                unsigned bl[2] = {b2l.x, b2l.y};
                mma8(s[j], qh[ks], bh);
                mma8(s[j], qh[ks], bl);
                mma8(s[j], ql[ks], bh);
            }
        }

        // online softmax
        float mx0 = -1e30f, mx1 = -1e30f;
        #pragma unroll
        for (int j = 0; j < 8; j++) {
            int cb = j * 8 + 2 * lq;
            float ms0 = Ms[cb], ms1 = Ms[cb + 1];
            s[j][0] = s[j][0] * 0.125f + ms0;
            s[j][1] = s[j][1] * 0.125f + ms1;
            s[j][2] = s[j][2] * 0.125f + ms0;
            s[j][3] = s[j][3] * 0.125f + ms1;
            mx0 = fmaxf(mx0, fmaxf(s[j][0], s[j][1]));
            mx1 = fmaxf(mx1, fmaxf(s[j][2], s[j][3]));
        }
        #pragma unroll
        for (int off = 1; off < 4; off <<= 1) {
            mx0 = fmaxf(mx0, __shfl_xor_sync(0xffffffffu, mx0, off));
            mx1 = fmaxf(mx1, __shfl_xor_sync(0xffffffffu, mx1, off));
        }
        float mn0 = fmaxf(m0r, mx0), mn1 = fmaxf(m1r, mx1);
        float a0 = expf(m0r - mn0),  a1 = expf(m1r - mn1);
        m0r = mn0; m1r = mn1;
        #pragma unroll
        for (int j2 = 0; j2 < 8; j2++) {
            o[j2][0] *= a0; o[j2][1] *= a0; o[j2][2] *= a1; o[j2][3] *= a1;
        }

        float rs0 = 0.f, rs1 = 0.f;
        const int sA = lq >> 1, sB = sA + 2;
        const bool od = lq & 1;
        #pragma unroll
        for (int j = 0; j < 8; j++) {
            float p00 = expf(s[j][0] - mn0);
            float p01 = expf(s[j][1] - mn0);
            float p10 = expf(s[j][2] - mn1);
            float p11 = expf(s[j][3] - mn1);
            rs0 += p00 + p01; rs1 += p10 + p11;
            // quad-local permutation: S fragment -> A fragment (natural key order)
            float g0 = __shfl_sync(0xffffffffu, p00, sA, 4);
            float g1 = __shfl_sync(0xffffffffu, p01, sA, 4);
            float h0 = __shfl_sync(0xffffffffu, p10, sA, 4);
            float h1 = __shfl_sync(0xffffffffu, p11, sA, 4);
            float e0 = __shfl_sync(0xffffffffu, p00, sB, 4);
            float e1 = __shfl_sync(0xffffffffu, p01, sB, 4);
            float f0 = __shfl_sync(0xffffffffu, p10, sB, 4);
            float f1 = __shfl_sync(0xffffffffu, p11, sB, 4);
            float A0 = od ? g1 : g0;
            float A1 = od ? h1 : h0;
            float A2 = od ? e1 : e0;
            float A3 = od ? f1 : f0;
            unsigned ah[4], al[4];
            ah[0] = f2tf(A0); al[0] = f2tf(A0 - __uint_as_float(ah[0]));
            ah[1] = f2tf(A1); al[1] = f2tf(A1 - __uint_as_float(ah[1]));
            ah[2] = f2tf(A2); al[2] = f2tf(A2 - __uint_as_float(ah[2]));
            ah[3] = f2tf(A3); al[3] = f2tf(A3 - __uint_as_float(ah[3]));
            // O += P_chunk_j * V_chunk_j
            #pragma unroll
            for (int j2 = 0; j2 < 8; j2++) {
                int n = j2 * 8 + ln4;
                uint2 bb = *(uint2*)&Vh[n*LDA + 8*j + 2*lq];
                uint2 cc = *(uint2*)&Vl[n*LDA + 8*j + 2*lq];
                unsigned bh2[2] = {bb.x, bb.y};
                unsigned bl2[2] = {cc.x, cc.y};
                mma8(o[j2], ah, bh2);
                mma8(o[j2], ah, bl2);
                mma8(o[j2], al, bh2);
            }
        }
        #pragma unroll
        for (int off = 1; off < 4; off <<= 1) {
            rs0 += __shfl_xor_sync(0xffffffffu, rs0, off);
            rs1 += __shfl_xor_sync(0xffffffffu, rs1, off);
        }
        l0 = l0 * a0 + rs0;
        l1 = l1 * a1 + rs1;
    }

    float i0 = 1.f / l0, i1 = 1.f / l1;
    int gq = q0 + rr;
    #pragma unroll
    for (int j = 0; j < 8; j++) {
        int col = h * 64 + j * 8 + 2 * lq;
        *(float2*)(ctx + (size_t)gq * Dv + col)     = make_float2(o[j][0]*i0, o[j][1]*i0);
        *(float2*)(ctx + (size_t)(gq+8) * Dv + col) = make_float2(o[j][2]*i1, o[j][3]*i1);
    }
}

// ---------------- SimHash codes ----------------
__global__ void coden_kernel()
{
    int idx = blockIdx.x * 256 + threadIdx.x;
    if (idx >= LTv * NCv) return;
    int n = idx & (NCv - 1), l = idx >> 12;
    int code = 0;
    #pragma unroll
    for (int kk = 0; kk < KHv; kk++)
        if (g_projn[(size_t)(l * KHv + kk) * NCv + n] > 0.f) code |= (1 << kk);
    g_coden[l * NCv + n] = code;
}

__global__ void codet_hist_kernel()
{
    int idx = blockIdx.x * 256 + threadIdx.x;
    if (idx >= LTv * NTOK) return;
    int tt = idx & (NTOK - 1), l = idx >> 11;
    int code = 0;
    #pragma unroll
    for (int kk = 0; kk < KHv; kk++)
        if (g_projt[(size_t)(l * KHv + kk) * NTOK + tt] > 0.f) code |= (1 << kk);
    int ch = tt >> 10;
    atomicAdd(&g_hist[(ch * LTv + l) * NBv + code], 1);
}

__global__ void score_kernel()
{
    int idx = blockIdx.x * 256 + threadIdx.x;
    if (idx >= 2 * NCv) return;
    int ch = idx >> 12, n = idx & (NCv - 1);
    const int* hist = g_hist + ch * LTv * NBv;
    int s = 0;
    #pragma unroll
    for (int l = 0; l < LTv; l++) s += hist[l * NBv + g_coden[l * NCv + n]];
    g_score[idx] = s;
}

// ---------------- stable top-S selection (block = chunk) ----------------
__global__ void select_kernel()
{
    __shared__ int ssc[NCv];
    __shared__ int red[1024];
    const int ch = blockIdx.x;
    const int* score = g_score + ch * NCv;
    int* sids = g_sids + ch * SSv;
    int tid = threadIdx.x;
    for (int i = tid; i < NCv; i += 1024) ssc[i] = score[i];
    __syncthreads();

    int lo = 0, hi = LTv * TPPv + 1;
    while (lo + 1 < hi) {
        int mid = (lo + hi) >> 1;
        int c = 0;
        for (int i = tid; i < NCv; i += 1024) c += (ssc[i] >= mid);
        red[tid] = c; __syncthreads();
        for (int st = 512; st > 0; st >>= 1) { if (tid < st) red[tid] += red[tid + st]; __syncthreads(); }
        int tot = red[0]; __syncthreads();
        if (tot >= SSv) lo = mid; else hi = mid;
    }
    int tau = lo;
    int c = 0;
    for (int i = tid; i < NCv; i += 1024) c += (ssc[i] > tau);
    red[tid] = c; __syncthreads();
    for (int st = 512; st > 0; st >>= 1) { if (tid < st) red[tid] += red[tid + st]; __syncthreads(); }
    int m = red[0];
    int need = SSv - m;
    __syncthreads();

    int base = tid * 4;
    int gtp[4], eqp[4];
    int lgt = 0, leq = 0;
    #pragma unroll
    for (int j = 0; j < 4; j++) {
        int sc = ssc[base + j];
        gtp[j] = lgt; eqp[j] = leq;
        lgt += (sc > tau); leq += (sc == tau);
    }
    red[tid] = (lgt << 16) | leq; __syncthreads();
    for (int off = 1; off < 1024; off <<= 1) {
        int vv = (tid >= off) ? red[tid - off] : 0;
        __syncthreads();
        red[tid] += vv;
        __syncthreads();
    }
    int excl = (tid == 0) ? 0 : red[tid - 1];
    int egt = excl >> 16, eeq = excl & 0xffff;
    #pragma unroll
    for (int j = 0; j < 4; j++) {
        int sc = ssc[base + j];
        if (sc > tau)                                sids[egt + gtp[j]] = base + j;
        else if (sc == tau && (eeq + eqp[j]) < need) sids[m + eeq + eqp[j]] = base + j;
    }
}

// ---------------- gathers ----------------
__global__ void gather_kernel(const float* __restrict__ W1, const float* __restrict__ b1)
{
    int idx = blockIdx.x * 256 + threadIdx.x;
    if (idx >= 2 * SSv * Dv) return;
    int ch = idx >> 20;
    int s = (idx >> 10) & 1023, dcol = idx & 1023;
    int row = g_sids[ch * SSv + s];
    g_w1s[idx] = W1[(size_t)row * Dv + dcol];
    if (dcol == 0) g_b1s[ch * SSv + s] = b1[row];
}
__global__ void gatherT_kernel(const float* __restrict__ W2)
{
    __shared__ float tile[32][33];
    int ch = blockIdx.x / (SSv / 32);
    int s0 = (blockIdx.x % (SSv / 32)) * 32, d0 = blockIdx.y * 32;
    int tx = threadIdx.x & 31, ty8 = threadIdx.x >> 5;
    for (int r = ty8; r < 32; r += 8) {
        int row = g_sids[ch * SSv + s0 + r];
        tile[r][tx] = W2[(size_t)row * Dv + d0 + tx];
    }
    __syncthreads();
    float* dst = g_w2sT + (size_t)ch * Dv * SSv;
    for (int r = ty8; r < 32; r += 8)
        dst[(size_t)(d0 + r) * SSv + s0 + tx] = tile[tx][r];
}
__global__ void tanhpns_kernel()
{
    int idx = blockIdx.x * 256 + threadIdx.x;
    if (idx >= 2 * SSv * LKv) return;
    int ch = idx >> 17;
    int s = (idx >> 7) & 1023, lk = idx & 127;
    int row = g_sids[ch * SSv + s];
    g_tanhpns[idx] = tanhf(g_projn[(size_t)lk * NCv + row]);
}

// ---------------- triplet loss ----------------
__global__ void __launch_bounds__(256)
triplet2()
{
    __shared__ float vals[8][1024];
    int w = threadIdx.x >> 5, lane = threadIdx.x & 31;
    int t = blockIdx.x * 8 + w;
    int ch = t >> 10;
    const float* lrow = g_logits + (size_t)t * SSv;
    const float* tpns = g_tanhpns + (size_t)ch * SSv * LKv;

    float apos = 0.f, aneg = 0.f;
    for (int phase = 0; phase < 2; phase++) {
        for (int i = lane; i < 256; i += 32)
            ((float4*)vals[w])[i] = ((const float4*)lrow)[i];
        __syncwarp();
        float sv[4] = {0.f, 0.f, 0.f, 0.f};
        for (int it = 0; it < PPv; it++) {
            float bv = (phase == 0) ? -1e30f : 1e30f;
            int bi = 1 << 30;
            #pragma unroll
            for (int qd = 0; qd < 32; qd++) {
                int i = lane + (qd << 5);
                float x = vals[w][i];
                bool better = (phase == 0) ? (x > bv) : (x < bv);
                if (better) { bv = x; bi = i; }
            }
            #pragma unroll
            for (int off = 16; off > 0; off >>= 1) {
                float ov = __shfl_xor_sync(0xffffffffu, bv, off);
                int   oi = __shfl_xor_sync(0xffffffffu, bi, off);
                bool take = (phase == 0)
                    ? (ov > bv || (ov == bv && oi < bi))
                    : (ov < bv || (ov == bv && oi < bi));
                if (take) { bv = ov; bi = oi; }
            }
            #pragma unroll
            for (int c2 = 0; c2 < 4; c2++)
                sv[c2] += tpns[(size_t)bi * LKv + lane + 32 * c2];
            if (lane == 0) vals[w][bi] = (phase == 0) ? -1e30f : 1e30f;
            __syncwarp();
        }
        float a = 0.f;
        #pragma unroll
        for (int c2 = 0; c2 < 4; c2++)
            a += sv[c2] * g_tanhpt[(size_t)t * LKv + lane + 32 * c2];
        #pragma unroll
        for (int off = 16; off > 0; off >>= 1)
            a += __shfl_xor_sync(0xffffffffu, a, off);
        a *= 1.0f / (128.0f * 64.0f);
        if (phase == 0) apos = a; else aneg = a;
    }
    if (lane == 0) g_trip[t] = fmaxf(aneg - apos + 0.5f, 0.f);
}

__global__ void trip_reduce(float* __restrict__ outp)
{
    __shared__ float red[1024];
    int tid = threadIdx.x;
    red[tid] = g_trip[tid] + g_trip[tid + 1024];
    __syncthreads();
    for (int st = 512; st > 0; st >>= 1) { if (tid < st) red[tid] += red[tid + st]; __syncthreads(); }
    if (tid == 0) *outp = red[0] * (1.0f / 2048.0f);
}

// ---------------- host ----------------
extern "C" void kernel_launch(void* const* d_in, const int* in_sizes, int n_in,
                              void* d_out, int out_size)
{
    const float* hidden = (const float*)d_in[0];
    const float* amask  = (const float*)d_in[1];
    const float* ln1_g  = (const float*)d_in[2];
    const float* ln1_b  = (const float*)d_in[3];
    const float* Wq     = (const float*)d_in[4];
    const float* bq     = (const float*)d_in[5];
    const float* Wk     = (const float*)d_in[6];
    const float* bk     = (const float*)d_in[7];
    const float* Wv     = (const float*)d_in[8];
    const float* bv     = (const float*)d_in[9];
    const float* Wo     = (const float*)d_in[10];
    const float* bo     = (const float*)d_in[11];
    const float* ln2_g  = (const float*)d_in[12];
    const float* ln2_b  = (const float*)d_in[13];
    const float* W1     = (const float*)d_in[14];
    const float* b1     = (const float*)d_in[15];
    const float* Whash  = (const float*)d_in[16];
    const float* W2     = (const float*)d_in[17];
    const float* b2     = (const float*)d_in[18];
    float* out = (float*)d_out;

    float *xln, *v, *ctx, *attn, *normed, *projn, *projt;
    float *w1s, *w2sT, *b1s, *logits, *acts;
    unsigned *qh, *ql, *kh, *kl, *vth, *vtl;
    int* histp;
    cudaGetSymbolAddress((void**)&xln,    g_xln);
    cudaGetSymbolAddress((void**)&qh,     g_qh);
    cudaGetSymbolAddress((void**)&ql,     g_ql);
    cudaGetSymbolAddress((void**)&kh,     g_kh);
    cudaGetSymbolAddress((void**)&kl,     g_kl);
    cudaGetSymbolAddress((void**)&v,      g_v);
    cudaGetSymbolAddress((void**)&vth,    g_vth);
    cudaGetSymbolAddress((void**)&vtl,    g_vtl);
    cudaGetSymbolAddress((void**)&ctx,    g_ctx);
    cudaGetSymbolAddress((void**)&attn,   g_attn);
    cudaGetSymbolAddress((void**)&normed, g_normed);
    cudaGetSymbolAddress((void**)&projn,  g_projn);
    cudaGetSymbolAddress((void**)&projt,  g_projt);
    cudaGetSymbolAddress((void**)&w1s,    g_w1s);
    cudaGetSymbolAddress((void**)&w2sT,   g_w2sT);
    cudaGetSymbolAddress((void**)&b1s,    g_b1s);
    cudaGetSymbolAddress((void**)&logits, g_logits);
    cudaGetSymbolAddress((void**)&acts,   g_acts);
    cudaGetSymbolAddress((void**)&histp,  g_hist);

    const int SM3  = (128 + 128) * 36 * 4 * 2;   // 73728
    const int SM1  = (64 + 128) * 36 * 4;        // 27648
    const int SMA  = 4 * 64 * LDA * 4 + 256;     // 73984
    cudaFuncSetAttribute((const void*)mma_nt<3,3,true,false,128,128,false,0>,
                         cudaFuncAttributeMaxDynamicSharedMemorySize, SM3);
    cudaFuncSetAttribute((const void*)mma_nt<3,0,true,false,128,128,false,0>,
                         cudaFuncAttributeMaxDynamicSharedMemorySize, SM3);
    cudaFuncSetAttribute((const void*)mma_nt<3,0,true,true,128,128,false,0>,
                         cudaFuncAttributeMaxDynamicSharedMemorySize, SM3);
    cudaFuncSetAttribute((const void*)mma_nt<1,1,true,false,64,128,true,SSv>,
                         cudaFuncAttributeMaxDynamicSharedMemorySize, SM1);
    cudaFuncSetAttribute((const void*)mma_nt<1,0,true,true,64,128,true,0>,
                         cudaFuncAttributeMaxDynamicSharedMemorySize, SM1);
    cudaFuncSetAttribute((const void*)attn5,
                         cudaFuncAttributeMaxDynamicSharedMemorySize, SMA);

    // ---- attention path ----
    ln_kernel<<<SQv, 256>>>(hidden, ln1_g, ln1_b, xln);
    msk_kernel<<<SQv/256, 256>>>(amask);
    dim3 gA(Dv/128, SQv/128);
    mma_nt<3,3,true,false,128,128,false,0><<<gA, 256, SM3>>>(xln, Wq, bq, nullptr,
                                                             (float*)qh, (float*)ql, SQv, Dv, Dv);
    mma_nt<3,3,true,false,128,128,false,0><<<gA, 256, SM3>>>(xln, Wk, bk, nullptr,
                                                             (float*)kh, (float*)kl, SQv, Dv, Dv);
    mma_nt<3,0,true,false,128,128,false,0><<<gA, 256, SM3>>>(xln, Wv, bv, nullptr,
                                                             v, nullptr, SQv, Dv, Dv);
    vtrans_kernel<<<dim3(SQv/32, Dv/32), 256>>>(v);
    attn5<<<dim3(SQv/64, Hv), 128, SMA>>>(qh, ql, kh, kl, vth, vtl, ctx);
    mma_nt<3,0,true,true,128,128,false,0><<<gA, 256, SM3>>>(ctx, Wo, bo, hidden,
                                                            attn, nullptr, SQv, Dv, Dv);

    // ---- FFN prep ----
    ln_kernel<<<SQv, 256>>>(attn, ln2_g, ln2_b, normed);
    gemm_nt<false,false><<<dim3(NCv/64, LKv/64), 256>>>(Whash, W1, nullptr, projn, LKv, NCv, Dv);
    coden_kernel<<<(LTv * NCv) / 256, 256>>>();

    // ---- LSH FFN (chunks fused in non-GEMM parts) ----
    gemm_nt<false,true><<<dim3(NTOK/64, LKv/64), 256>>>(Whash, normed, nullptr, projt, LKv, NTOK, Dv);
    cudaMemsetAsync(histp, 0, 2 * LTv * NBv * sizeof(int), 0);
    codet_hist_kernel<<<(LTv * NTOK) / 256, 256>>>();
    score_kernel<<<(2 * NCv) / 256, 256>>>();
    select_kernel<<<2, 1024>>>();
    gather_kernel<<<(2 * SSv * Dv) / 256, 256>>>(W1, b1);
    gatherT_kernel<<<dim3(2 * SSv / 32, Dv / 32), 256>>>(W2);
    tanhpns_kernel<<<(2 * SSv * LKv) / 256, 256>>>();

    // logits + fused GELU (both chunks, chunk-select B/bias)
    mma_nt<1,1,true,false,64,128,true,SSv><<<dim3(SSv/128, NTOK/64), 256, SM1>>>(
        normed, w1s, b1s, nullptr, logits, acts, NTOK, SSv, Dv);
    triplet2<<<NTOK/8, 256>>>();
    // out = acts @ W2s^T + b2 + attn residual (both chunks)
    mma_nt<1,0,true,true,64,128,true,0><<<dim3(Dv/128, NTOK/64), 256, SM1>>>(
        acts, w2sT, b2, attn, out, nullptr, NTOK, Dv, SSv);

    // ---- scalar output ----
    trip_reduce<<<1, 1024>>>(out + (size_t)SQv * Dv);
}

// round 12
// speedup vs baseline: 1.0937x; 1.0937x over previous
#include <cuda_runtime.h>
#include <math.h>
#include <stddef.h>

// ---------------- problem constants ----------------
#define SQv   2048
#define Dv    1024
#define Hv    16
#define DHv   64
#define NCv   4096
#define LTv   16
#define KHv   8
#define LKv   128
#define NBv   256
#define TPPv  1024
#define SSv   1024
#define PPv   64
#define NTOK  2048

// ---------------- device scratch ----------------
__device__ __align__(16) float    g_xln   [SQv*Dv];
__device__ __align__(16) unsigned g_qh    [SQv*Dv];
__device__ __align__(16) unsigned g_ql    [SQv*Dv];
__device__ __align__(16) unsigned g_kh    [SQv*Dv];
__device__ __align__(16) unsigned g_kl    [SQv*Dv];
__device__ __align__(16) unsigned g_vh    [SQv*Dv];
__device__ __align__(16) unsigned g_vl    [SQv*Dv];
__device__ __align__(16) float    g_ctx   [SQv*Dv];
__device__ __align__(16) float    g_attn  [SQv*Dv];
__device__ __align__(16) float    g_normed[SQv*Dv];
__device__ __align__(16) float    g_msk   [SQv];
__device__ __align__(16) float    g_projn [LKv*NCv];
__device__ __align__(16) float    g_projt [LKv*NTOK];
__device__ __align__(16) float    g_tanhpt[NTOK*LKv];
__device__ __align__(16) float    g_tanhpns[2*SSv*LKv];
__device__ __align__(16) float    g_w1s   [2*SSv*Dv];
__device__ __align__(16) float    g_w2sT  [2*(size_t)Dv*SSv];
__device__ __align__(16) float    g_b1s   [2*SSv];
__device__ __align__(16) float    g_logits[NTOK*SSv];
__device__ __align__(16) float    g_acts  [NTOK*SSv];
__device__ __align__(16) float    g_trip  [NTOK];
__device__ int g_coden[LTv*NCv];
__device__ int g_hist [2*LTv*NBv];
__device__ int g_score[2*NCv];
__device__ int g_sids [2*SSv];

// ---------------- helpers ----------------
__device__ __forceinline__ unsigned f2tf(float x){
    unsigned u; asm("cvt.rna.tf32.f32 %0, %1;" : "=r"(u) : "f"(x)); return u;
}
__device__ __forceinline__ void mma8(float* d, const unsigned* a, const unsigned* b){
    asm volatile("mma.sync.aligned.m16n8k8.row.col.f32.tf32.tf32.f32 "
        "{%0,%1,%2,%3},{%4,%5,%6,%7},{%8,%9},{%0,%1,%2,%3};"
        : "+f"(d[0]), "+f"(d[1]), "+f"(d[2]), "+f"(d[3])
        : "r"(a[0]), "r"(a[1]), "r"(a[2]), "r"(a[3]), "r"(b[0]), "r"(b[1]));
}
__device__ __forceinline__ float gelu_exact(float x){
    return 0.5f * x * (1.f + erff(x * 0.70710678118654752f));
}
__device__ __forceinline__ unsigned s2u(const void* p){
    return (unsigned)__cvta_generic_to_shared(p);
}
__device__ __forceinline__ void cpa16(unsigned dst, const void* src){
    asm volatile("cp.async.ca.shared.global [%0], [%1], 16;" :: "r"(dst), "l"(src));
}
__device__ __forceinline__ void cpa_commit(){ asm volatile("cp.async.commit_group;"); }
__device__ __forceinline__ void cpa_wait0(){ asm volatile("cp.async.wait_group 0;" ::: "memory"); }

// ---------------- LayerNorm ----------------
__global__ void ln_kernel(const float* __restrict__ x, const float* __restrict__ g,
                          const float* __restrict__ b, float* __restrict__ y)
{
    int row = blockIdx.x;
    const float* xr = x + (size_t)row * Dv;
    __shared__ float red[256];
    int tid = threadIdx.x;
    float s = 0.f, ss = 0.f;
    for (int i = tid; i < Dv; i += 256) { float v = xr[i]; s += v; ss += v * v; }
    red[tid] = s; __syncthreads();
    for (int st = 128; st > 0; st >>= 1) { if (tid < st) red[tid] += red[tid + st]; __syncthreads(); }
    float mean = red[0] / Dv;
    __syncthreads();
    red[tid] = ss; __syncthreads();
    for (int st = 128; st > 0; st >>= 1) { if (tid < st) red[tid] += red[tid + st]; __syncthreads(); }
    float var = red[0] / Dv - mean * mean;
    float inv = rsqrtf(var + 1e-12f);
    float* yr = y + (size_t)row * Dv;
    for (int i = tid; i < Dv; i += 256) yr[i] = (xr[i] - mean) * inv * g[i] + b[i];
}

__global__ void msk_kernel(const float* __restrict__ mask)
{
    int i = blockIdx.x * 256 + threadIdx.x;
    if (i < SQv) g_msk[i] = -1000.f * (1.f - mask[i]);
}

// ---------------- TF32 tensor-core GEMM NT (round-8 hot loop) ----------------
// EPI=0: C fp32. EPI=1: C fp32 + gelu(C)->C2. EPI=2: split hi->C, lo->C2 (u32).
// CHSEL: one-time per-CTA B/bias select for merged 2-chunk GEMMs (row block >= TPPv).
template<int SPLIT, int EPI, bool BIAS, bool RES, int BM_, int BN_, bool CHSEL, int BIASZ>
__global__ void __launch_bounds__(256, 1)
mma_nt(const float* __restrict__ A, const float* __restrict__ B,
       const float* __restrict__ bias, const float* __restrict__ res,
       float* __restrict__ C, float* __restrict__ C2, int M, int N, int K)
{
    constexpr int BK = 32, LD = 36;
    constexpr int WTM = BM_ / 2, WTN = BN_ / 4;
    constexpr int MT = WTM / 16, NT = WTN / 8;
    extern __shared__ unsigned sm[];
    unsigned* Ah = sm;
    unsigned* Bh = Ah + BM_ * LD;
    unsigned* Al = (SPLIT == 3) ? Bh + BN_ * LD : Ah;
    unsigned* Bl = (SPLIT == 3) ? Al + BM_ * LD : Bh;

    if (CHSEL) {
        if ((int)(blockIdx.y * BM_) >= TPPv) {
            B += (size_t)SSv * Dv;
            bias += BIASZ;
        }
    }

    const int tid = threadIdx.x;
    const int lane = tid & 31, wid = tid >> 5;
    const int wm = wid & 1, wn = wid >> 1;
    const int m0 = blockIdx.y * BM_, n0 = blockIdx.x * BN_;

    constexpr int PA = BM_ / 32;
    constexpr int PB = BN_ / 32;
    const int lrw = tid >> 3;
    const int lcc = (tid & 7) * 4;

    float4 pa[PA], pb[PB];
    float acc[MT][NT][4];
    #pragma unroll
    for (int i = 0; i < MT; i++)
        #pragma unroll
        for (int j = 0; j < NT; j++)
            #pragma unroll
            for (int u = 0; u < 4; u++) acc[i][j][u] = 0.f;

    #pragma unroll
    for (int p = 0; p < PA; p++)
        pa[p] = *(const float4*)(A + (size_t)(m0 + p*32 + lrw) * K + lcc);
    #pragma unroll
    for (int p = 0; p < PB; p++)
        pb[p] = *(const float4*)(B + (size_t)(n0 + p*32 + lrw) * K + lcc);

    const int ntiles = K / BK;
    for (int kt = 0; kt < ntiles; kt++) {
        __syncthreads();
        #pragma unroll
        for (int p = 0; p < PA; p++) {
            float vv[4] = {pa[p].x, pa[p].y, pa[p].z, pa[p].w};
            #pragma unroll
            for (int i = 0; i < 4; i++) {
                unsigned h = f2tf(vv[i]);
                Ah[(p*32 + lrw) * LD + lcc + i] = h;
                if (SPLIT == 3)
                    Al[(p*32 + lrw) * LD + lcc + i] = f2tf(vv[i] - __uint_as_float(h));
            }
        }
        #pragma unroll
        for (int p = 0; p < PB; p++) {
            float vv[4] = {pb[p].x, pb[p].y, pb[p].z, pb[p].w};
            #pragma unroll
            for (int i = 0; i < 4; i++) {
                unsigned h = f2tf(vv[i]);
                Bh[(p*32 + lrw) * LD + lcc + i] = h;
                if (SPLIT == 3)
                    Bl[(p*32 + lrw) * LD + lcc + i] = f2tf(vv[i] - __uint_as_float(h));
            }
        }
        __syncthreads();
        if (kt + 1 < ntiles) {
            const float* An = A + (size_t)(kt + 1) * BK;
            const float* Bn = B + (size_t)(kt + 1) * BK;
            #pragma unroll
            for (int p = 0; p < PA; p++)
                pa[p] = *(const float4*)(An + (size_t)(m0 + p*32 + lrw) * K + lcc);
            #pragma unroll
            for (int p = 0; p < PB; p++)
                pb[p] = *(const float4*)(Bn + (size_t)(n0 + p*32 + lrw) * K + lcc);
        }
        #pragma unroll
        for (int ks = 0; ks < 4; ks++) {
            unsigned ah[MT][4], al[MT][4], bh[NT][2], bl[NT][2];
            #pragma unroll
            for (int i = 0; i < MT; i++) {
                int r = wm * WTM + i * 16 + (lane >> 2);
                int c = ks * 8 + (lane & 3);
                ah[i][0] = Ah[r*LD + c];       ah[i][1] = Ah[(r+8)*LD + c];
                ah[i][2] = Ah[r*LD + c + 4];   ah[i][3] = Ah[(r+8)*LD + c + 4];
                if (SPLIT == 3) {
                    al[i][0] = Al[r*LD + c];     al[i][1] = Al[(r+8)*LD + c];
                    al[i][2] = Al[r*LD + c + 4]; al[i][3] = Al[(r+8)*LD + c + 4];
                }
            }
            #pragma unroll
            for (int j = 0; j < NT; j++) {
                int r = wn * WTN + j * 8 + (lane >> 2);
                int c = ks * 8 + (lane & 3);
                bh[j][0] = Bh[r*LD + c];  bh[j][1] = Bh[r*LD + c + 4];
                if (SPLIT == 3) {
                    bl[j][0] = Bl[r*LD + c];  bl[j][1] = Bl[r*LD + c + 4];
                }
            }
            #pragma unroll
            for (int i = 0; i < MT; i++)
                #pragma unroll
                for (int j = 0; j < NT; j++) {
                    mma8(acc[i][j], ah[i], bh[j]);
                    if (SPLIT == 3) {
                        mma8(acc[i][j], ah[i], bl[j]);
                        mma8(acc[i][j], al[i], bh[j]);
                    }
                }
        }
    }
    #pragma unroll
    for (int i = 0; i < MT; i++) {
        #pragma unroll
        for (int j = 0; j < NT; j++) {
            int r = m0 + wm * WTM + i * 16 + (lane >> 2);
            int c = n0 + wn * WTN + j * 8 + (lane & 3) * 2;
            float v00 = acc[i][j][0], v01 = acc[i][j][1];
            float v10 = acc[i][j][2], v11 = acc[i][j][3];
            if (BIAS) { float b0 = bias[c], b1 = bias[c+1]; v00 += b0; v01 += b1; v10 += b0; v11 += b1; }
            if (RES) {
                v00 += res[(size_t)r*N + c];     v01 += res[(size_t)r*N + c + 1];
                v10 += res[(size_t)(r+8)*N + c]; v11 += res[(size_t)(r+8)*N + c + 1];
            }
            if (EPI == 2) {
                unsigned* Chi = (unsigned*)C;
                unsigned* Clo = (unsigned*)C2;
                unsigned h00 = f2tf(v00), h01 = f2tf(v01), h10 = f2tf(v10), h11 = f2tf(v11);
                *(uint2*)(Chi + (size_t)r*N + c)     = make_uint2(h00, h01);
                *(uint2*)(Chi + (size_t)(r+8)*N + c) = make_uint2(h10, h11);
                *(uint2*)(Clo + (size_t)r*N + c)     =
                    make_uint2(f2tf(v00 - __uint_as_float(h00)), f2tf(v01 - __uint_as_float(h01)));
                *(uint2*)(Clo + (size_t)(r+8)*N + c) =
                    make_uint2(f2tf(v10 - __uint_as_float(h10)), f2tf(v11 - __uint_as_float(h11)));
            } else {
                *(float2*)(C + (size_t)r*N + c)     = make_float2(v00, v01);
                *(float2*)(C + (size_t)(r+8)*N + c) = make_float2(v10, v11);
                if (EPI == 1) {
                    *(float2*)(C2 + (size_t)r*N + c)     = make_float2(gelu_exact(v00), gelu_exact(v01));
                    *(float2*)(C2 + (size_t)(r+8)*N + c) = make_float2(gelu_exact(v10), gelu_exact(v11));
                }
            }
        }
    }
}

// ---------------- exact-fp32 GEMM NT (hash projections) ----------------
// TANHT: also write tanh(C) transposed into g_tanhpt[t][lk]
template<bool HAS_BIAS, bool TANHT>
__global__ void gemm_nt(const float* __restrict__ A, const float* __restrict__ Bm,
                        const float* __restrict__ bias,
                        float* __restrict__ C, int M, int N, int Kd)
{
    __shared__ float As[16][64];
    __shared__ float Bs[16][64];
    int tid = threadIdx.x;
    int tx = tid & 15, ty = tid >> 4;
    int m0 = blockIdx.y * 64, n0 = blockIdx.x * 64;
    float acc[4][4] = {};
    for (int k0 = 0; k0 < Kd; k0 += 16) {
        int idx = tid * 4;
        int r = idx >> 4, kk = idx & 15;
        float4 av = *(const float4*)(A  + (size_t)(m0 + r) * Kd + k0 + kk);
        As[kk+0][r] = av.x; As[kk+1][r] = av.y; As[kk+2][r] = av.z; As[kk+3][r] = av.w;
        float4 bv = *(const float4*)(Bm + (size_t)(n0 + r) * Kd + k0 + kk);
        Bs[kk+0][r] = bv.x; Bs[kk+1][r] = bv.y; Bs[kk+2][r] = bv.z; Bs[kk+3][r] = bv.w;
        __syncthreads();
        #pragma unroll
        for (int q = 0; q < 16; q++) {
            float a[4], b[4];
            #pragma unroll
            for (int i = 0; i < 4; i++) a[i] = As[q][ty*4+i];
            #pragma unroll
            for (int j = 0; j < 4; j++) b[j] = Bs[q][tx*4+j];
            #pragma unroll
            for (int i = 0; i < 4; i++)
                #pragma unroll
                for (int j = 0; j < 4; j++)
                    acc[i][j] += a[i] * b[j];
        }
        __syncthreads();
    }
    #pragma unroll
    for (int i = 0; i < 4; i++) {
        int m = m0 + ty*4 + i;
        #pragma unroll
        for (int j = 0; j < 4; j++) {
            int n = n0 + tx*4 + j;
            float v = acc[i][j];
            if (HAS_BIAS) v += bias[n];
            C[(size_t)m * N + n] = v;
            if (TANHT) g_tanhpt[(size_t)n * LKv + m] = tanhf(v);
        }
    }
}

// ---------------- attention: 3xTF32 flash on pre-split inputs (round-8) ----------------
#define LDQ 68
#define LDVt 72
__global__ void __launch_bounds__(128, 2)
attn4(const unsigned* __restrict__ qh_g, const unsigned* __restrict__ ql_g,
      const unsigned* __restrict__ kh_g, const unsigned* __restrict__ kl_g,
      const unsigned* __restrict__ vh_g, const unsigned* __restrict__ vl_g,
      float* __restrict__ ctx)
{
    extern __shared__ unsigned sm[];
    unsigned* QPh = sm;
    unsigned* QPl = QPh + 64*LDQ;
    unsigned* Kh  = QPl + 64*LDQ;
    unsigned* Kl  = Kh  + 64*LDQ;
    unsigned* Vh  = Kl  + 64*LDQ;
    unsigned* Vl  = Vh  + 64*LDVt;
    float*    Ms  = (float*)(Vl + 64*LDVt);

    const int tid = threadIdx.x;
    const int lane = tid & 31, w = tid >> 5;
    const int h = blockIdx.y, q0 = blockIdx.x * 64;
    const int rr = w * 16 + (lane >> 2);

    const unsigned uQPh = s2u(QPh), uQPl = s2u(QPl);
    const unsigned uKh = s2u(Kh), uKl = s2u(Kl), uVh = s2u(Vh), uVl = s2u(Vl);
    const unsigned uMs = s2u(Ms);

    #pragma unroll
    for (int p = 0; p < 8; p++) {
        int idx = tid + p * 128;
        int row = idx >> 4, c4 = (idx & 15) * 4;
        size_t gof = (size_t)(q0 + row) * Dv + h * 64 + c4;
        unsigned sof = (row * LDQ + c4) * 4;
        cpa16(uQPh + sof, qh_g + gof);
        cpa16(uQPl + sof, ql_g + gof);
    }
    cpa_commit(); cpa_wait0();
    __syncthreads();

    unsigned qh[8][4], ql[8][4];
    #pragma unroll
    for (int ks = 0; ks < 8; ks++) {
        int c = ks * 8 + (lane & 3);
        qh[ks][0] = QPh[rr*LDQ + c];       qh[ks][1] = QPh[(rr+8)*LDQ + c];
        qh[ks][2] = QPh[rr*LDQ + c + 4];   qh[ks][3] = QPh[(rr+8)*LDQ + c + 4];
        ql[ks][0] = QPl[rr*LDQ + c];       ql[ks][1] = QPl[(rr+8)*LDQ + c];
        ql[ks][2] = QPl[rr*LDQ + c + 4];   ql[ks][3] = QPl[(rr+8)*LDQ + c + 4];
    }

    float o[8][4];
    #pragma unroll
    for (int j = 0; j < 8; j++)
        #pragma unroll
        for (int u = 0; u < 4; u++) o[j][u] = 0.f;
    float m0r = -1e30f, m1r = -1e30f, l0 = 0.f, l1 = 0.f;

    for (int kt = 0; kt < SQv / 64; kt++) {
        int k0 = kt * 64;
        __syncthreads();
        #pragma unroll
        for (int p = 0; p < 8; p++) {
            int idx = tid + p * 128;
            int row = idx >> 4, c4 = (idx & 15) * 4;
            size_t gof = (size_t)(k0 + row) * Dv + h * 64 + c4;
            unsigned sK = (row * LDQ + c4) * 4;
            unsigned sV = (row * LDVt + c4) * 4;
            cpa16(uKh + sK, kh_g + gof);
            cpa16(uKl + sK, kl_g + gof);
            cpa16(uVh + sV, vh_g + gof);
            cpa16(uVl + sV, vl_g + gof);
        }
        if (tid < 16) cpa16(uMs + tid * 16, g_msk + k0 + tid * 4);
        cpa_commit(); cpa_wait0();
        __syncthreads();

        float s[8][4];
        #pragma unroll
        for (int j = 0; j < 8; j++)
            #pragma unroll
            for (int u = 0; u < 4; u++) s[j][u] = 0.f;
        #pragma unroll
        for (int ks = 0; ks < 8; ks++) {
            #pragma unroll
            for (int j = 0; j < 8; j++) {
                int r = j * 8 + (lane >> 2);
                int c = ks * 8 + (lane & 3);
                unsigned bh[2], bl[2];
                bh[0] = Kh[r*LDQ + c];  bh[1] = Kh[r*LDQ + c + 4];
                bl[0] = Kl[r*LDQ + c];  bl[1] = Kl[r*LDQ + c + 4];
                mma8(s[j], qh[ks], bh);
                mma8(s[j], qh[ks], bl);
                mma8(s[j], ql[ks], bh);
            }
        }

        float mx0 = -1e30f, mx1 = -1e30f;
        #pragma unroll
        for (int j = 0; j < 8; j++) {
            int cb = j * 8 + (lane & 3) * 2;
            float ms0 = Ms[cb], ms1 = Ms[cb + 1];
            s[j][0] = s[j][0] * 0.125f + ms0;
            s[j][1] = s[j][1] * 0.125f + ms1;
            s[j][2] = s[j][2] * 0.125f + ms0;
            s[j][3] = s[j][3] * 0.125f + ms1;
            mx0 = fmaxf(mx0, fmaxf(s[j][0], s[j][1]));
            mx1 = fmaxf(mx1, fmaxf(s[j][2], s[j][3]));
        }
        #pragma unroll
        for (int off = 1; off < 4; off <<= 1) {
            mx0 = fmaxf(mx0, __shfl_xor_sync(0xffffffffu, mx0, off));
            mx1 = fmaxf(mx1, __shfl_xor_sync(0xffffffffu, mx1, off));
        }
        float mn0 = fmaxf(m0r, mx0), mn1 = fmaxf(m1r, mx1);
        float a0 = expf(m0r - mn0),  a1 = expf(m1r - mn1);
        m0r = mn0; m1r = mn1;
        float rs0 = 0.f, rs1 = 0.f;
        #pragma unroll
        for (int j = 0; j < 8; j++) {
            int cb = j * 8 + (lane & 3) * 2;
            float p00 = expf(s[j][0] - mn0);
            float p01 = expf(s[j][1] - mn0);
            float p10 = expf(s[j][2] - mn1);
            float p11 = expf(s[j][3] - mn1);
            rs0 += p00 + p01; rs1 += p10 + p11;
            unsigned hh;
            hh = f2tf(p00); QPh[rr*LDQ + cb]       = hh; QPl[rr*LDQ + cb]       = f2tf(p00 - __uint_as_float(hh));
            hh = f2tf(p01); QPh[rr*LDQ + cb + 1]   = hh; QPl[rr*LDQ + cb + 1]   = f2tf(p01 - __uint_as_float(hh));
            hh = f2tf(p10); QPh[(rr+8)*LDQ + cb]   = hh; QPl[(rr+8)*LDQ + cb]   = f2tf(p10 - __uint_as_float(hh));
            hh = f2tf(p11); QPh[(rr+8)*LDQ + cb+1] = hh; QPl[(rr+8)*LDQ + cb+1] = f2tf(p11 - __uint_as_float(hh));
            o[j][0] *= a0; o[j][1] *= a0; o[j][2] *= a1; o[j][3] *= a1;
        }
        #pragma unroll
        for (int off = 1; off < 4; off <<= 1) {
            rs0 += __shfl_xor_sync(0xffffffffu, rs0, off);
            rs1 += __shfl_xor_sync(0xffffffffu, rs1, off);
        }
        l0 = l0 * a0 + rs0;
        l1 = l1 * a1 + rs1;
        __syncwarp();

        #pragma unroll
        for (int ks = 0; ks < 8; ks++) {
            int c = ks * 8 + (lane & 3);
            unsigned ah[4], al[4];
            ah[0] = QPh[rr*LDQ + c];     ah[1] = QPh[(rr+8)*LDQ + c];
            ah[2] = QPh[rr*LDQ + c + 4]; ah[3] = QPh[(rr+8)*LDQ + c + 4];
            al[0] = QPl[rr*LDQ + c];     al[1] = QPl[(rr+8)*LDQ + c];
            al[2] = QPl[rr*LDQ + c + 4]; al[3] = QPl[(rr+8)*LDQ + c + 4];
            #pragma unroll
            for (int j = 0; j < 8; j++) {
                int n = j * 8 + (lane >> 2);
                unsigned bh[2], bl[2];
                bh[0] = Vh[(ks*8 + (lane&3)) * LDVt + n];
                bh[1] = Vh[(ks*8 + (lane&3) + 4) * LDVt + n];
                bl[0] = Vl[(ks*8 + (lane&3)) * LDVt + n];
                bl[1] = Vl[(ks*8 + (lane&3) + 4) * LDVt + n];
                mma8(o[j], ah, bh);
                mma8(o[j], ah, bl);
                mma8(o[j], al, bh);
            }
        }
    }

    float i0 = 1.f / l0, i1 = 1.f / l1;
    int gq = q0 + rr;
    #pragma unroll
    for (int j = 0; j < 8; j++) {
        int col = h * 64 + j * 8 + (lane & 3) * 2;
        *(float2*)(ctx + (size_t)gq * Dv + col)     = make_float2(o[j][0]*i0, o[j][1]*i0);
        *(float2*)(ctx + (size_t)(gq+8) * Dv + col) = make_float2(o[j][2]*i1, o[j][3]*i1);
    }
}

// ---------------- SimHash codes ----------------
__global__ void coden_kernel()
{
    int idx = blockIdx.x * 256 + threadIdx.x;
    if (idx >= LTv * NCv) return;
    int n = idx & (NCv - 1), l = idx >> 12;
    int code = 0;
    #pragma unroll
    for (int kk = 0; kk < KHv; kk++)
        if (g_projn[(size_t)(l * KHv + kk) * NCv + n] > 0.f) code |= (1 << kk);
    g_coden[l * NCv + n] = code;
}

__global__ void codet_hist_kernel()
{
    int idx = blockIdx.x * 256 + threadIdx.x;
    if (idx >= LTv * NTOK) return;
    int tt = idx & (NTOK - 1), l = idx >> 11;
    int code = 0;
    #pragma unroll
    for (int kk = 0; kk < KHv; kk++)
        if (g_projt[(size_t)(l * KHv + kk) * NTOK + tt] > 0.f) code |= (1 << kk);
    int ch = tt >> 10;
    atomicAdd(&g_hist[(ch * LTv + l) * NBv + code], 1);
}

__global__ void score_kernel()
{
    int idx = blockIdx.x * 256 + threadIdx.x;
    if (idx >= 2 * NCv) return;
    int ch = idx >> 12, n = idx & (NCv - 1);
    const int* hist = g_hist + ch * LTv * NBv;
    int s = 0;
    #pragma unroll
    for (int l = 0; l < LTv; l++) s += hist[l * NBv + g_coden[l * NCv + n]];
    g_score[idx] = s;
}

// ---------------- stable top-S selection (block = chunk) ----------------
__global__ void select_kernel()
{
    __shared__ int ssc[NCv];
    __shared__ int red[1024];
    const int ch = blockIdx.x;
    const int* score = g_score + ch * NCv;
    int* sids = g_sids + ch * SSv;
    int tid = threadIdx.x;
    for (int i = tid; i < NCv; i += 1024) ssc[i] = score[i];
    __syncthreads();

    int lo = 0, hi = LTv * TPPv + 1;
    while (lo + 1 < hi) {
        int mid = (lo + hi) >> 1;
        int c = 0;
        for (int i = tid; i < NCv; i += 1024) c += (ssc[i] >= mid);
        red[tid] = c; __syncthreads();
        for (int st = 512; st > 0; st >>= 1) { if (tid < st) red[tid] += red[tid + st]; __syncthreads(); }
        int tot = red[0]; __syncthreads();
        if (tot >= SSv) lo = mid; else hi = mid;
    }
    int tau = lo;
    int c = 0;
    for (int i = tid; i < NCv; i += 1024) c += (ssc[i] > tau);
    red[tid] = c; __syncthreads();
    for (int st = 512; st > 0; st >>= 1) { if (tid < st) red[tid] += red[tid + st]; __syncthreads(); }
    int m = red[0];
    int need = SSv - m;
    __syncthreads();

    int base = tid * 4;
    int gtp[4], eqp[4];
    int lgt = 0, leq = 0;
    #pragma unroll
    for (int j = 0; j < 4; j++) {
        int sc = ssc[base + j];
        gtp[j] = lgt; eqp[j] = leq;
        lgt += (sc > tau); leq += (sc == tau);
    }
    red[tid] = (lgt << 16) | leq; __syncthreads();
    for (int off = 1; off < 1024; off <<= 1) {
        int vv = (tid >= off) ? red[tid - off] : 0;
        __syncthreads();
        red[tid] += vv;
        __syncthreads();
    }
    int excl = (tid == 0) ? 0 : red[tid - 1];
    int egt = excl >> 16, eeq = excl & 0xffff;
    #pragma unroll
    for (int j = 0; j < 4; j++) {
        int sc = ssc[base + j];
        if (sc > tau)                                sids[egt + gtp[j]] = base + j;
        else if (sc == tau && (eeq + eqp[j]) < need) sids[m + eeq + eqp[j]] = base + j;
    }
}

// ---------------- gathers ----------------
__global__ void gather_kernel(const float* __restrict__ W1, const float* __restrict__ b1)
{
    int idx = blockIdx.x * 256 + threadIdx.x;
    if (idx >= 2 * SSv * Dv) return;
    int ch = idx >> 20;
    int s = (idx >> 10) & 1023, dcol = idx & 1023;
    int row = g_sids[ch * SSv + s];
    g_w1s[idx] = W1[(size_t)row * Dv + dcol];
    if (dcol == 0) g_b1s[ch * SSv + s] = b1[row];
}
__global__ void gatherT_kernel(const float* __restrict__ W2)
{
    __shared__ float tile[32][33];
    int ch = blockIdx.x / (SSv / 32);
    int s0 = (blockIdx.x % (SSv / 32)) * 32, d0 = blockIdx.y * 32;
    int tx = threadIdx.x & 31, ty8 = threadIdx.x >> 5;
    for (int r = ty8; r < 32; r += 8) {
        int row = g_sids[ch * SSv + s0 + r];
        tile[r][tx] = W2[(size_t)row * Dv + d0 + tx];
    }
    __syncthreads();
    float* dst = g_w2sT + (size_t)ch * Dv * SSv;
    for (int r = ty8; r < 32; r += 8)
        dst[(size_t)(d0 + r) * SSv + s0 + tx] = tile[tx][r];
}
__global__ void tanhpns_kernel()
{
    int idx = blockIdx.x * 256 + threadIdx.x;
    if (idx >= 2 * SSv * LKv) return;
    int ch = idx >> 17;
    int s = (idx >> 7) & 1023, lk = idx & 127;
    int row = g_sids[ch * SSv + s];
    g_tanhpns[idx] = tanhf(g_projn[(size_t)lk * NCv + row]);
}

// ---------------- triplet loss ----------------
__global__ void __launch_bounds__(256)
triplet2()
{
    __shared__ float vals[8][1024];
    int w = threadIdx.x >> 5, lane = threadIdx.x & 31;
    int t = blockIdx.x * 8 + w;
    int ch = t >> 10;
    const float* lrow = g_logits + (size_t)t * SSv;
    const float* tpns = g_tanhpns + (size_t)ch * SSv * LKv;

    float apos = 0.f, aneg = 0.f;
    for (int phase = 0; phase < 2; phase++) {
        for (int i = lane; i < 256; i += 32)
            ((float4*)vals[w])[i] = ((const float4*)lrow)[i];
        __syncwarp();
        float sv[4] = {0.f, 0.f, 0.f, 0.f};
        for (int it = 0; it < PPv; it++) {
            float bv = (phase == 0) ? -1e30f : 1e30f;
            int bi = 1 << 30;
            #pragma unroll
            for (int qd = 0; qd < 32; qd++) {
                int i = lane + (qd << 5);
                float x = vals[w][i];
                bool better = (phase == 0) ? (x > bv) : (x < bv);
                if (better) { bv = x; bi = i; }
            }
            #pragma unroll
            for (int off = 16; off > 0; off >>= 1) {
                float ov = __shfl_xor_sync(0xffffffffu, bv, off);
                int   oi = __shfl_xor_sync(0xffffffffu, bi, off);
                bool take = (phase == 0)
                    ? (ov > bv || (ov == bv && oi < bi))
                    : (ov < bv || (ov == bv && oi < bi));
                if (take) { bv = ov; bi = oi; }
            }
            #pragma unroll
            for (int c2 = 0; c2 < 4; c2++)
                sv[c2] += tpns[(size_t)bi * LKv + lane + 32 * c2];
            if (lane == 0) vals[w][bi] = (phase == 0) ? -1e30f : 1e30f;
            __syncwarp();
        }
        float a = 0.f;
        #pragma unroll
        for (int c2 = 0; c2 < 4; c2++)
            a += sv[c2] * g_tanhpt[(size_t)t * LKv + lane + 32 * c2];
        #pragma unroll
        for (int off = 16; off > 0; off >>= 1)
            a += __shfl_xor_sync(0xffffffffu, a, off);
        a *= 1.0f / (128.0f * 64.0f);
        if (phase == 0) apos = a; else aneg = a;
    }
    if (lane == 0) g_trip[t] = fmaxf(aneg - apos + 0.5f, 0.f);
}

__global__ void trip_reduce(float* __restrict__ outp)
{
    __shared__ float red[1024];
    int tid = threadIdx.x;
    red[tid] = g_trip[tid] + g_trip[tid + 1024];
    __syncthreads();
    for (int st = 512; st > 0; st >>= 1) { if (tid < st) red[tid] += red[tid + st]; __syncthreads(); }
    if (tid == 0) *outp = red[0] * (1.0f / 2048.0f);
}

// ---------------- host ----------------
extern "C" void kernel_launch(void* const* d_in, const int* in_sizes, int n_in,
                              void* d_out, int out_size)
{
    const float* hidden = (const float*)d_in[0];
    const float* amask  = (const float*)d_in[1];
    const float* ln1_g  = (const float*)d_in[2];
    const float* ln1_b  = (const float*)d_in[3];
    const float* Wq     = (const float*)d_in[4];
    const float* bq     = (const float*)d_in[5];
    const float* Wk     = (const float*)d_in[6];
    const float* bk     = (const float*)d_in[7];
    const float* Wv     = (const float*)d_in[8];
    const float* bv     = (const float*)d_in[9];
    const float* Wo     = (const float*)d_in[10];
    const float* bo     = (const float*)d_in[11];
    const float* ln2_g  = (const float*)d_in[12];
    const float* ln2_b  = (const float*)d_in[13];
    const float* W1     = (const float*)d_in[14];
    const float* b1     = (const float*)d_in[15];
    const float* Whash  = (const float*)d_in[16];
    const float* W2     = (const float*)d_in[17];
    const float* b2     = (const float*)d_in[18];
    float* out = (float*)d_out;

    float *xln, *ctx, *attn, *normed, *projn, *projt;
    float *w1s, *w2sT, *b1s, *logits, *acts;
    unsigned *qh, *ql, *kh, *kl, *vh, *vl;
    int* histp;
    cudaGetSymbolAddress((void**)&xln,    g_xln);
    cudaGetSymbolAddress((void**)&qh,     g_qh);
    cudaGetSymbolAddress((void**)&ql,     g_ql);
    cudaGetSymbolAddress((void**)&kh,     g_kh);
    cudaGetSymbolAddress((void**)&kl,     g_kl);
    cudaGetSymbolAddress((void**)&vh,     g_vh);
    cudaGetSymbolAddress((void**)&vl,     g_vl);
    cudaGetSymbolAddress((void**)&ctx,    g_ctx);
    cudaGetSymbolAddress((void**)&attn,   g_attn);
    cudaGetSymbolAddress((void**)&normed, g_normed);
    cudaGetSymbolAddress((void**)&projn,  g_projn);
    cudaGetSymbolAddress((void**)&projt,  g_projt);
    cudaGetSymbolAddress((void**)&w1s,    g_w1s);
    cudaGetSymbolAddress((void**)&w2sT,   g_w2sT);
    cudaGetSymbolAddress((void**)&b1s,    g_b1s);
    cudaGetSymbolAddress((void**)&logits, g_logits);
    cudaGetSymbolAddress((void**)&acts,   g_acts);
    cudaGetSymbolAddress((void**)&histp,  g_hist);

    const int SM3  = (128 + 128) * 36 * 4 * 2;   // 73728
    const int SM1  = (64 + 128) * 36 * 4;        // 27648
    const int SMAT = (4*64*LDQ + 2*64*LDVt) * 4 + 64*4;
    cudaFuncSetAttribute((const void*)mma_nt<3,2,true,false,128,128,false,0>,
                         cudaFuncAttributeMaxDynamicSharedMemorySize, SM3);
    cudaFuncSetAttribute((const void*)mma_nt<3,0,true,true,128,128,false,0>,
                         cudaFuncAttributeMaxDynamicSharedMemorySize, SM3);
    cudaFuncSetAttribute((const void*)mma_nt<1,1,true,false,64,128,true,SSv>,
                         cudaFuncAttributeMaxDynamicSharedMemorySize, SM1);
    cudaFuncSetAttribute((const void*)mma_nt<1,0,true,true,64,128,true,0>,
                         cudaFuncAttributeMaxDynamicSharedMemorySize, SM1);
    cudaFuncSetAttribute((const void*)attn4,
                         cudaFuncAttributeMaxDynamicSharedMemorySize, SMAT);

    // ---- attention path ----
    ln_kernel<<<SQv, 256>>>(hidden, ln1_g, ln1_b, xln);
    msk_kernel<<<SQv/256, 256>>>(amask);
    dim3 gA(Dv/128, SQv/128);
    mma_nt<3,2,true,false,128,128,false,0><<<gA, 256, SM3>>>(xln, Wq, bq, nullptr,
                                                             (float*)qh, (float*)ql, SQv, Dv, Dv);
    mma_nt<3,2,true,false,128,128,false,0><<<gA, 256, SM3>>>(xln, Wk, bk, nullptr,
                                                             (float*)kh, (float*)kl, SQv, Dv, Dv);
    mma_nt<3,2,true,false,128,128,false,0><<<gA, 256, SM3>>>(xln, Wv, bv, nullptr,
                                                             (float*)vh, (float*)vl, SQv, Dv, Dv);
    attn4<<<dim3(SQv/64, Hv), 128, SMAT>>>(qh, ql, kh, kl, vh, vl, ctx);
    mma_nt<3,0,true,true,128,128,false,0><<<gA, 256, SM3>>>(ctx, Wo, bo, hidden,
                                                            attn, nullptr, SQv, Dv, Dv);

    // ---- FFN prep ----
    ln_kernel<<<SQv, 256>>>(attn, ln2_g, ln2_b, normed);
    gemm_nt<false,false><<<dim3(NCv/64, LKv/64), 256>>>(Whash, W1, nullptr, projn, LKv, NCv, Dv);
    coden_kernel<<<(LTv * NCv) / 256, 256>>>();

    // ---- LSH FFN (chunks fused, round-8 small kernels + TANHT fusion) ----
    gemm_nt<false,true><<<dim3(NTOK/64, LKv/64), 256>>>(Whash, normed, nullptr, projt, LKv, NTOK, Dv);
    cudaMemsetAsync(histp, 0, 2 * LTv * NBv * sizeof(int), 0);
    codet_hist_kernel<<<(LTv * NTOK) / 256, 256>>>();
    score_kernel<<<(2 * NCv) / 256, 256>>>();
    select_kernel<<<2, 1024>>>();
    gather_kernel<<<(2 * SSv * Dv) / 256, 256>>>(W1, b1);
    gatherT_kernel<<<dim3(2 * SSv / 32, Dv / 32), 256>>>(W2);
    tanhpns_kernel<<<(2 * SSv * LKv) / 256, 256>>>();

    // logits + fused GELU (both chunks, one launch via CHSEL)
    mma_nt<1,1,true,false,64,128,true,SSv><<<dim3(SSv/128, NTOK/64), 256, SM1>>>(
        normed, w1s, b1s, nullptr, logits, acts, NTOK, SSv, Dv);
    triplet2<<<NTOK/8, 256>>>();
    // out = acts @ W2s^T + b2 + attn residual (both chunks, one launch)
    mma_nt<1,0,true,true,64,128,true,0><<<dim3(Dv/128, NTOK/64), 256, SM1>>>(
        acts, w2sT, b2, attn, out, nullptr, NTOK, Dv, SSv);

    // ---- scalar output ----
    trip_reduce<<<1, 1024>>>(out + (size_t)SQv * Dv);
}

// round 16
// speedup vs baseline: 1.1439x; 1.0459x over previous
#include <cuda_runtime.h>
#include <math.h>
#include <stddef.h>

// ---------------- problem constants ----------------
#define SQv   2048
#define Dv    1024
#define Hv    16
#define DHv   64
#define NCv   4096
#define LTv   16
#define KHv   8
#define LKv   128
#define NBv   256
#define TPPv  1024
#define SSv   1024
#define PPv   64
#define NTOK  2048

// ---------------- device scratch ----------------
__device__ __align__(16) float    g_xln   [SQv*Dv];
__device__ __align__(16) unsigned g_qh    [SQv*Dv];
__device__ __align__(16) unsigned g_ql    [SQv*Dv];
__device__ __align__(16) unsigned g_kh    [SQv*Dv];
__device__ __align__(16) unsigned g_kl    [SQv*Dv];
__device__ __align__(16) unsigned g_vh    [SQv*Dv];
__device__ __align__(16) unsigned g_vl    [SQv*Dv];
__device__ __align__(16) float    g_ctx   [SQv*Dv];
__device__ __align__(16) float    g_attn  [SQv*Dv];
__device__ __align__(16) float    g_normed[SQv*Dv];
__device__ __align__(16) float    g_msk   [SQv];
__device__ __align__(16) float    g_projn [LKv*NCv];
__device__ __align__(16) float    g_projt [LKv*NTOK];
__device__ __align__(16) float    g_tanhpt[NTOK*LKv];
__device__ __align__(16) float    g_tanhpns[2*SSv*LKv];
__device__ __align__(16) float    g_w1s   [2*SSv*Dv];
__device__ __align__(16) float    g_w2sT  [2*(size_t)Dv*SSv];
__device__ __align__(16) float    g_b1s   [2*SSv];
__device__ __align__(16) float    g_logits[NTOK*SSv];
__device__ __align__(16) float    g_acts  [NTOK*SSv];
__device__ __align__(16) float    g_trip  [NTOK];
__device__ int g_coden[LTv*NCv];
__device__ int g_hist [2*LTv*NBv];
__device__ int g_score[2*NCv];
__device__ int g_sids [2*SSv];

// ---------------- helpers ----------------
__device__ __forceinline__ unsigned f2tf(float x){
    unsigned u; asm("cvt.rna.tf32.f32 %0, %1;" : "=r"(u) : "f"(x)); return u;
}
__device__ __forceinline__ void mma8(float* d, const unsigned* a, const unsigned* b){
    asm volatile("mma.sync.aligned.m16n8k8.row.col.f32.tf32.tf32.f32 "
        "{%0,%1,%2,%3},{%4,%5,%6,%7},{%8,%9},{%0,%1,%2,%3};"
        : "+f"(d[0]), "+f"(d[1]), "+f"(d[2]), "+f"(d[3])
        : "r"(a[0]), "r"(a[1]), "r"(a[2]), "r"(a[3]), "r"(b[0]), "r"(b[1]));
}
__device__ __forceinline__ float gelu_exact(float x){
    return 0.5f * x * (1.f + erff(x * 0.70710678118654752f));
}
__device__ __forceinline__ unsigned s2u(const void* p){
    return (unsigned)__cvta_generic_to_shared(p);
}
__device__ __forceinline__ void cpa16(unsigned dst, const void* src){
    asm volatile("cp.async.ca.shared.global [%0], [%1], 16;" :: "r"(dst), "l"(src));
}
__device__ __forceinline__ void cpa_commit(){ asm volatile("cp.async.commit_group;"); }
__device__ __forceinline__ void cpa_wait0(){ asm volatile("cp.async.wait_group 0;" ::: "memory"); }

// ---------------- LayerNorm ----------------
__global__ void ln_kernel(const float* __restrict__ x, const float* __restrict__ g,
                          const float* __restrict__ b, float* __restrict__ y)
{
    int row = blockIdx.x;
    const float* xr = x + (size_t)row * Dv;
    __shared__ float red[256];
    int tid = threadIdx.x;
    float s = 0.f, ss = 0.f;
    for (int i = tid; i < Dv; i += 256) { float v = xr[i]; s += v; ss += v * v; }
    red[tid] = s; __syncthreads();
    for (int st = 128; st > 0; st >>= 1) { if (tid < st) red[tid] += red[tid + st]; __syncthreads(); }
    float mean = red[0] / Dv;
    __syncthreads();
    red[tid] = ss; __syncthreads();
    for (int st = 128; st > 0; st >>= 1) { if (tid < st) red[tid] += red[tid + st]; __syncthreads(); }
    float var = red[0] / Dv - mean * mean;
    float inv = rsqrtf(var + 1e-12f);
    float* yr = y + (size_t)row * Dv;
    for (int i = tid; i < Dv; i += 256) yr[i] = (xr[i] - mean) * inv * g[i] + b[i];
}

__global__ void msk_kernel(const float* __restrict__ mask)
{
    int i = blockIdx.x * 256 + threadIdx.x;
    if (i < SQv) g_msk[i] = -1000.f * (1.f - mask[i]);
}

// ---------------- TF32 tensor-core GEMM NT (round-8 hot loop) ----------------
// EPI=0: C fp32. EPI=1: C fp32 + gelu(C)->C2. EPI=2: split hi->C, lo->C2 (u32).
// CHSEL: one-time per-CTA B/bias select for merged 2-chunk GEMMs (row block >= TPPv).
template<int SPLIT, int EPI, bool BIAS, bool RES, int BM_, int BN_, bool CHSEL, int BIASZ>
__global__ void __launch_bounds__(256, 1)
mma_nt(const float* __restrict__ A, const float* __restrict__ B,
       const float* __restrict__ bias, const float* __restrict__ res,
       float* __restrict__ C, float* __restrict__ C2, int M, int N, int K)
{
    constexpr int BK = 32, LD = 36;
    constexpr int WTM = BM_ / 2, WTN = BN_ / 4;
    constexpr int MT = WTM / 16, NT = WTN / 8;
    extern __shared__ unsigned sm[];
    unsigned* Ah = sm;
    unsigned* Bh = Ah + BM_ * LD;
    unsigned* Al = (SPLIT == 3) ? Bh + BN_ * LD : Ah;
    unsigned* Bl = (SPLIT == 3) ? Al + BM_ * LD : Bh;

    if (CHSEL) {
        if ((int)(blockIdx.y * BM_) >= TPPv) {
            B += (size_t)SSv * Dv;
            bias += BIASZ;
        }
    }

    const int tid = threadIdx.x;
    const int lane = tid & 31, wid = tid >> 5;
    const int wm = wid & 1, wn = wid >> 1;
    const int m0 = blockIdx.y * BM_, n0 = blockIdx.x * BN_;

    constexpr int PA = BM_ / 32;
    constexpr int PB = BN_ / 32;
    const int lrw = tid >> 3;
    const int lcc = (tid & 7) * 4;

    float4 pa[PA], pb[PB];
    float acc[MT][NT][4];
    #pragma unroll
    for (int i = 0; i < MT; i++)
        #pragma unroll
        for (int j = 0; j < NT; j++)
            #pragma unroll
            for (int u = 0; u < 4; u++) acc[i][j][u] = 0.f;

    #pragma unroll
    for (int p = 0; p < PA; p++)
        pa[p] = *(const float4*)(A + (size_t)(m0 + p*32 + lrw) * K + lcc);
    #pragma unroll
    for (int p = 0; p < PB; p++)
        pb[p] = *(const float4*)(B + (size_t)(n0 + p*32 + lrw) * K + lcc);

    const int ntiles = K / BK;
    for (int kt = 0; kt < ntiles; kt++) {
        __syncthreads();
        #pragma unroll
        for (int p = 0; p < PA; p++) {
            float vv[4] = {pa[p].x, pa[p].y, pa[p].z, pa[p].w};
            #pragma unroll
            for (int i = 0; i < 4; i++) {
                unsigned h = f2tf(vv[i]);
                Ah[(p*32 + lrw) * LD + lcc + i] = h;
                if (SPLIT == 3)
                    Al[(p*32 + lrw) * LD + lcc + i] = f2tf(vv[i] - __uint_as_float(h));
            }
        }
        #pragma unroll
        for (int p = 0; p < PB; p++) {
            float vv[4] = {pb[p].x, pb[p].y, pb[p].z, pb[p].w};
            #pragma unroll
            for (int i = 0; i < 4; i++) {
                unsigned h = f2tf(vv[i]);
                Bh[(p*32 + lrw) * LD + lcc + i] = h;
                if (SPLIT == 3)
                    Bl[(p*32 + lrw) * LD + lcc + i] = f2tf(vv[i] - __uint_as_float(h));
            }
        }
        __syncthreads();
        if (kt + 1 < ntiles) {
            const float* An = A + (size_t)(kt + 1) * BK;
            const float* Bn = B + (size_t)(kt + 1) * BK;
            #pragma unroll
            for (int p = 0; p < PA; p++)
                pa[p] = *(const float4*)(An + (size_t)(m0 + p*32 + lrw) * K + lcc);
            #pragma unroll
            for (int p = 0; p < PB; p++)
                pb[p] = *(const float4*)(Bn + (size_t)(n0 + p*32 + lrw) * K + lcc);
        }
        #pragma unroll
        for (int ks = 0; ks < 4; ks++) {
            unsigned ah[MT][4], al[MT][4], bh[NT][2], bl[NT][2];
            #pragma unroll
            for (int i = 0; i < MT; i++) {
                int r = wm * WTM + i * 16 + (lane >> 2);
                int c = ks * 8 + (lane & 3);
                ah[i][0] = Ah[r*LD + c];       ah[i][1] = Ah[(r+8)*LD + c];
                ah[i][2] = Ah[r*LD + c + 4];   ah[i][3] = Ah[(r+8)*LD + c + 4];
                if (SPLIT == 3) {
                    al[i][0] = Al[r*LD + c];     al[i][1] = Al[(r+8)*LD + c];
                    al[i][2] = Al[r*LD + c + 4]; al[i][3] = Al[(r+8)*LD + c + 4];
                }
            }
            #pragma unroll
            for (int j = 0; j < NT; j++) {
                int r = wn * WTN + j * 8 + (lane >> 2);
                int c = ks * 8 + (lane & 3);
                bh[j][0] = Bh[r*LD + c];  bh[j][1] = Bh[r*LD + c + 4];
                if (SPLIT == 3) {
                    bl[j][0] = Bl[r*LD + c];  bl[j][1] = Bl[r*LD + c + 4];
                }
            }
            #pragma unroll
            for (int i = 0; i < MT; i++)
                #pragma unroll
                for (int j = 0; j < NT; j++) {
                    mma8(acc[i][j], ah[i], bh[j]);
                    if (SPLIT == 3) {
                        mma8(acc[i][j], ah[i], bl[j]);
                        mma8(acc[i][j], al[i], bh[j]);
                    }
                }
        }
    }
    #pragma unroll
    for (int i = 0; i < MT; i++) {
        #pragma unroll
        for (int j = 0; j < NT; j++) {
            int r = m0 + wm * WTM + i * 16 + (lane >> 2);
            int c = n0 + wn * WTN + j * 8 + (lane & 3) * 2;
            float v00 = acc[i][j][0], v01 = acc[i][j][1];
            float v10 = acc[i][j][2], v11 = acc[i][j][3];
            if (BIAS) { float b0 = bias[c], b1 = bias[c+1]; v00 += b0; v01 += b1; v10 += b0; v11 += b1; }
            if (RES) {
                v00 += res[(size_t)r*N + c];     v01 += res[(size_t)r*N + c + 1];
                v10 += res[(size_t)(r+8)*N + c]; v11 += res[(size_t)(r+8)*N + c + 1];
            }
            if (EPI == 2) {
                unsigned* Chi = (unsigned*)C;
                unsigned* Clo = (unsigned*)C2;
                unsigned h00 = f2tf(v00), h01 = f2tf(v01), h10 = f2tf(v10), h11 = f2tf(v11);
                *(uint2*)(Chi + (size_t)r*N + c)     = make_uint2(h00, h01);
                *(uint2*)(Chi + (size_t)(r+8)*N + c) = make_uint2(h10, h11);
                *(uint2*)(Clo + (size_t)r*N + c)     =
                    make_uint2(f2tf(v00 - __uint_as_float(h00)), f2tf(v01 - __uint_as_float(h01)));
                *(uint2*)(Clo + (size_t)(r+8)*N + c) =
                    make_uint2(f2tf(v10 - __uint_as_float(h10)), f2tf(v11 - __uint_as_float(h11)));
            } else {
                *(float2*)(C + (size_t)r*N + c)     = make_float2(v00, v01);
                *(float2*)(C + (size_t)(r+8)*N + c) = make_float2(v10, v11);
                if (EPI == 1) {
                    *(float2*)(C2 + (size_t)r*N + c)     = make_float2(gelu_exact(v00), gelu_exact(v01));
                    *(float2*)(C2 + (size_t)(r+8)*N + c) = make_float2(gelu_exact(v10), gelu_exact(v11));
                }
            }
        }
    }
}

// ---------------- merged exact-fp32 hash GEMM ----------------
// part A (blockIdx.x < NCv/64): projn = Whash @ W1^T      [LK, NC]
// part B (else):                projt = Whash @ normed^T  [LK, NTOK] (+ tanh transposed)
__global__ void gemm_hash(const float* __restrict__ Whash, const float* __restrict__ W1,
                          const float* __restrict__ normed)
{
    __shared__ float As[16][64];
    __shared__ float Bs[16][64];
    int tid = threadIdx.x;
    int tx = tid & 15, ty = tid >> 4;

    const float* Bm; float* C; int N; int n0; bool tanht;
    if ((int)blockIdx.x < NCv / 64) {
        Bm = W1;     C = g_projn; N = NCv;  n0 = blockIdx.x * 64;              tanht = false;
    } else {
        Bm = normed; C = g_projt; N = NTOK; n0 = (blockIdx.x - NCv/64) * 64;   tanht = true;
    }
    int m0 = blockIdx.y * 64;

    float acc[4][4] = {};
    for (int k0 = 0; k0 < Dv; k0 += 16) {
        int idx = tid * 4;
        int r = idx >> 4, kk = idx & 15;
        float4 av = *(const float4*)(Whash + (size_t)(m0 + r) * Dv + k0 + kk);
        As[kk+0][r] = av.x; As[kk+1][r] = av.y; As[kk+2][r] = av.z; As[kk+3][r] = av.w;
        float4 bv = *(const float4*)(Bm + (size_t)(n0 + r) * Dv + k0 + kk);
        Bs[kk+0][r] = bv.x; Bs[kk+1][r] = bv.y; Bs[kk+2][r] = bv.z; Bs[kk+3][r] = bv.w;
        __syncthreads();
        #pragma unroll
        for (int q = 0; q < 16; q++) {
            float a[4], b[4];
            #pragma unroll
            for (int i = 0; i < 4; i++) a[i] = As[q][ty*4+i];
            #pragma unroll
            for (int j = 0; j < 4; j++) b[j] = Bs[q][tx*4+j];
            #pragma unroll
            for (int i = 0; i < 4; i++)
                #pragma unroll
                for (int j = 0; j < 4; j++)
                    acc[i][j] += a[i] * b[j];
        }
        __syncthreads();
    }
    #pragma unroll
    for (int i = 0; i < 4; i++) {
        int m = m0 + ty*4 + i;
        #pragma unroll
        for (int j = 0; j < 4; j++) {
            int n = n0 + tx*4 + j;
            float v = acc[i][j];
            C[(size_t)m * N + n] = v;
            if (tanht) g_tanhpt[(size_t)n * LKv + m] = tanhf(v);
        }
    }
}

// ---------------- attention: 3xTF32 flash on pre-split inputs (round-8) ----------------
#define LDQ 68
#define LDVt 72
__global__ void __launch_bounds__(128, 2)
attn4(const unsigned* __restrict__ qh_g, const unsigned* __restrict__ ql_g,
      const unsigned* __restrict__ kh_g, const unsigned* __restrict__ kl_g,
      const unsigned* __restrict__ vh_g, const unsigned* __restrict__ vl_g,
      float* __restrict__ ctx)
{
    extern __shared__ unsigned sm[];
    unsigned* QPh = sm;
    unsigned* QPl = QPh + 64*LDQ;
    unsigned* Kh  = QPl + 64*LDQ;
    unsigned* Kl  = Kh  + 64*LDQ;
    unsigned* Vh  = Kl  + 64*LDQ;
    unsigned* Vl  = Vh  + 64*LDVt;
    float*    Ms  = (float*)(Vl + 64*LDVt);

    const int tid = threadIdx.x;
    const int lane = tid & 31, w = tid >> 5;
    const int h = blockIdx.y, q0 = blockIdx.x * 64;
    const int rr = w * 16 + (lane >> 2);

    const unsigned uQPh = s2u(QPh), uQPl = s2u(QPl);
    const unsigned uKh = s2u(Kh), uKl = s2u(Kl), uVh = s2u(Vh), uVl = s2u(Vl);
    const unsigned uMs = s2u(Ms);

    #pragma unroll
    for (int p = 0; p < 8; p++) {
        int idx = tid + p * 128;
        int row = idx >> 4, c4 = (idx & 15) * 4;
        size_t gof = (size_t)(q0 + row) * Dv + h * 64 + c4;
        unsigned sof = (row * LDQ + c4) * 4;
        cpa16(uQPh + sof, qh_g + gof);
        cpa16(uQPl + sof, ql_g + gof);
    }
    cpa_commit(); cpa_wait0();
    __syncthreads();

    unsigned qh[8][4], ql[8][4];
    #pragma unroll
    for (int ks = 0; ks < 8; ks++) {
        int c = ks * 8 + (lane & 3);
        qh[ks][0] = QPh[rr*LDQ + c];       qh[ks][1] = QPh[(rr+8)*LDQ + c];
        qh[ks][2] = QPh[rr*LDQ + c + 4];   qh[ks][3] = QPh[(rr+8)*LDQ + c + 4];
        ql[ks][0] = QPl[rr*LDQ + c];       ql[ks][1] = QPl[(rr+8)*LDQ + c];
        ql[ks][2] = QPl[rr*LDQ + c + 4];   ql[ks][3] = QPl[(rr+8)*LDQ + c + 4];
    }

    float o[8][4];
    #pragma unroll
    for (int j = 0; j < 8; j++)
        #pragma unroll
        for (int u = 0; u < 4; u++) o[j][u] = 0.f;
    float m0r = -1e30f, m1r = -1e30f, l0 = 0.f, l1 = 0.f;

    for (int kt = 0; kt < SQv / 64; kt++) {
        int k0 = kt * 64;
        __syncthreads();
        #pragma unroll
        for (int p = 0; p < 8; p++) {
            int idx = tid + p * 128;
            int row = idx >> 4, c4 = (idx & 15) * 4;
            size_t gof = (size_t)(k0 + row) * Dv + h * 64 + c4;
            unsigned sK = (row * LDQ + c4) * 4;
            unsigned sV = (row * LDVt + c4) * 4;
            cpa16(uKh + sK, kh_g + gof);
            cpa16(uKl + sK, kl_g + gof);
            cpa16(uVh + sV, vh_g + gof);
            cpa16(uVl + sV, vl_g + gof);
        }
        if (tid < 16) cpa16(uMs + tid * 16, g_msk + k0 + tid * 4);
        cpa_commit(); cpa_wait0();
        __syncthreads();

        float s[8][4];
        #pragma unroll
        for (int j = 0; j < 8; j++)
            #pragma unroll
            for (int u = 0; u < 4; u++) s[j][u] = 0.f;
        #pragma unroll
        for (int ks = 0; ks < 8; ks++) {
            #pragma unroll
            for (int j = 0; j < 8; j++) {
                int r = j * 8 + (lane >> 2);
                int c = ks * 8 + (lane & 3);
                unsigned bh[2], bl[2];
                bh[0] = Kh[r*LDQ + c];  bh[1] = Kh[r*LDQ + c + 4];
                bl[0] = Kl[r*LDQ + c];  bl[1] = Kl[r*LDQ + c + 4];
                mma8(s[j], qh[ks], bh);
                mma8(s[j], qh[ks], bl);
                mma8(s[j], ql[ks], bh);
            }
        }

        float mx0 = -1e30f, mx1 = -1e30f;
        #pragma unroll
        for (int j = 0; j < 8; j++) {
            int cb = j * 8 + (lane & 3) * 2;
            float ms0 = Ms[cb], ms1 = Ms[cb + 1];
            s[j][0] = s[j][0] * 0.125f + ms0;
            s[j][1] = s[j][1] * 0.125f + ms1;
            s[j][2] = s[j][2] * 0.125f + ms0;
            s[j][3] = s[j][3] * 0.125f + ms1;
            mx0 = fmaxf(mx0, fmaxf(s[j][0], s[j][1]));
            mx1 = fmaxf(mx1, fmaxf(s[j][2], s[j][3]));
        }
        #pragma unroll
        for (int off = 1; off < 4; off <<= 1) {
            mx0 = fmaxf(mx0, __shfl_xor_sync(0xffffffffu, mx0, off));
            mx1 = fmaxf(mx1, __shfl_xor_sync(0xffffffffu, mx1, off));
        }
        float mn0 = fmaxf(m0r, mx0), mn1 = fmaxf(m1r, mx1);
        float a0 = expf(m0r - mn0),  a1 = expf(m1r - mn1);
        m0r = mn0; m1r = mn1;
        float rs0 = 0.f, rs1 = 0.f;
        #pragma unroll
        for (int j = 0; j < 8; j++) {
            int cb = j * 8 + (lane & 3) * 2;
            float p00 = expf(s[j][0] - mn0);
            float p01 = expf(s[j][1] - mn0);
            float p10 = expf(s[j][2] - mn1);
            float p11 = expf(s[j][3] - mn1);
            rs0 += p00 + p01; rs1 += p10 + p11;
            unsigned hh;
            hh = f2tf(p00); QPh[rr*LDQ + cb]       = hh; QPl[rr*LDQ + cb]       = f2tf(p00 - __uint_as_float(hh));
            hh = f2tf(p01); QPh[rr*LDQ + cb + 1]   = hh; QPl[rr*LDQ + cb + 1]   = f2tf(p01 - __uint_as_float(hh));
            hh = f2tf(p10); QPh[(rr+8)*LDQ + cb]   = hh; QPl[(rr+8)*LDQ + cb]   = f2tf(p10 - __uint_as_float(hh));
            hh = f2tf(p11); QPh[(rr+8)*LDQ + cb+1] = hh; QPl[(rr+8)*LDQ + cb+1] = f2tf(p11 - __uint_as_float(hh));
            o[j][0] *= a0; o[j][1] *= a0; o[j][2] *= a1; o[j][3] *= a1;
        }
        #pragma unroll
        for (int off = 1; off < 4; off <<= 1) {
            rs0 += __shfl_xor_sync(0xffffffffu, rs0, off);
            rs1 += __shfl_xor_sync(0xffffffffu, rs1, off);
        }
        l0 = l0 * a0 + rs0;
        l1 = l1 * a1 + rs1;
        __syncwarp();

        #pragma unroll
        for (int ks = 0; ks < 8; ks++) {
            int c = ks * 8 + (lane & 3);
            unsigned ah[4], al[4];
            ah[0] = QPh[rr*LDQ + c];     ah[1] = QPh[(rr+8)*LDQ + c];
            ah[2] = QPh[rr*LDQ + c + 4]; ah[3] = QPh[(rr+8)*LDQ + c + 4];
            al[0] = QPl[rr*LDQ + c];     al[1] = QPl[(rr+8)*LDQ + c];
            al[2] = QPl[rr*LDQ + c + 4]; al[3] = QPl[(rr+8)*LDQ + c + 4];
            #pragma unroll
            for (int j = 0; j < 8; j++) {
                int n = j * 8 + (lane >> 2);
                unsigned bh[2], bl[2];
                bh[0] = Vh[(ks*8 + (lane&3)) * LDVt + n];
                bh[1] = Vh[(ks*8 + (lane&3) + 4) * LDVt + n];
                bl[0] = Vl[(ks*8 + (lane&3)) * LDVt + n];
                bl[1] = Vl[(ks*8 + (lane&3) + 4) * LDVt + n];
                mma8(o[j], ah, bh);
                mma8(o[j], ah, bl);
                mma8(o[j], al, bh);
            }
        }
    }

    float i0 = 1.f / l0, i1 = 1.f / l1;
    int gq = q0 + rr;
    #pragma unroll
    for (int j = 0; j < 8; j++) {
        int col = h * 64 + j * 8 + (lane & 3) * 2;
        *(float2*)(ctx + (size_t)gq * Dv + col)     = make_float2(o[j][0]*i0, o[j][1]*i0);
        *(float2*)(ctx + (size_t)(gq+8) * Dv + col) = make_float2(o[j][2]*i1, o[j][3]*i1);
    }
}

// ---------------- SimHash codes ----------------
__global__ void coden_kernel()
{
    int idx = blockIdx.x * 256 + threadIdx.x;
    if (idx >= LTv * NCv) return;
    int n = idx & (NCv - 1), l = idx >> 12;
    int code = 0;
    #pragma unroll
    for (int kk = 0; kk < KHv; kk++)
        if (g_projn[(size_t)(l * KHv + kk) * NCv + n] > 0.f) code |= (1 << kk);
    g_coden[l * NCv + n] = code;
}

__global__ void codet_hist_kernel()
{
    int idx = blockIdx.x * 256 + threadIdx.x;
    if (idx >= LTv * NTOK) return;
    int tt = idx & (NTOK - 1), l = idx >> 11;
    int code = 0;
    #pragma unroll
    for (int kk = 0; kk < KHv; kk++)
        if (g_projt[(size_t)(l * KHv + kk) * NTOK + tt] > 0.f) code |= (1 << kk);
    int ch = tt >> 10;
    atomicAdd(&g_hist[(ch * LTv + l) * NBv + code], 1);
}

__global__ void score_kernel()
{
    int idx = blockIdx.x * 256 + threadIdx.x;
    if (idx >= 2 * NCv) return;
    int ch = idx >> 12, n = idx & (NCv - 1);
    const int* hist = g_hist + ch * LTv * NBv;
    int s = 0;
    #pragma unroll
    for (int l = 0; l < LTv; l++) s += hist[l * NBv + g_coden[l * NCv + n]];
    g_score[idx] = s;
}

// ---------------- stable top-S selection (block = chunk) ----------------
__global__ void select_kernel()
{
    __shared__ int ssc[NCv];
    __shared__ int red[1024];
    const int ch = blockIdx.x;
    const int* score = g_score + ch * NCv;
    int* sids = g_sids + ch * SSv;
    int tid = threadIdx.x;
    for (int i = tid; i < NCv; i += 1024) ssc[i] = score[i];
    __syncthreads();

    int lo = 0, hi = LTv * TPPv + 1;
    while (lo + 1 < hi) {
        int mid = (lo + hi) >> 1;
        int c = 0;
        for (int i = tid; i < NCv; i += 1024) c += (ssc[i] >= mid);
        red[tid] = c; __syncthreads();
        for (int st = 512; st > 0; st >>= 1) { if (tid < st) red[tid] += red[tid + st]; __syncthreads(); }
        int tot = red[0]; __syncthreads();
        if (tot >= SSv) lo = mid; else hi = mid;
    }
    int tau = lo;
    int c = 0;
    for (int i = tid; i < NCv; i += 1024) c += (ssc[i] > tau);
    red[tid] = c; __syncthreads();
    for (int st = 512; st > 0; st >>= 1) { if (tid < st) red[tid] += red[tid + st]; __syncthreads(); }
    int m = red[0];
    int need = SSv - m;
    __syncthreads();

    int base = tid * 4;
    int gtp[4], eqp[4];
    int lgt = 0, leq = 0;
    #pragma unroll
    for (int j = 0; j < 4; j++) {
        int sc = ssc[base + j];
        gtp[j] = lgt; eqp[j] = leq;
        lgt += (sc > tau); leq += (sc == tau);
    }
    red[tid] = (lgt << 16) | leq; __syncthreads();
    for (int off = 1; off < 1024; off <<= 1) {
        int vv = (tid >= off) ? red[tid - off] : 0;
        __syncthreads();
        red[tid] += vv;
        __syncthreads();
    }
    int excl = (tid == 0) ? 0 : red[tid - 1];
    int egt = excl >> 16, eeq = excl & 0xffff;
    #pragma unroll
    for (int j = 0; j < 4; j++) {
        int sc = ssc[base + j];
        if (sc > tau)                                sids[egt + gtp[j]] = base + j;
        else if (sc == tau && (eeq + eqp[j]) < need) sids[m + eeq + eqp[j]] = base + j;
    }
}

// ---------------- gathers ----------------
__global__ void gather_kernel(const float* __restrict__ W1, const float* __restrict__ b1)
{
    int idx = blockIdx.x * 256 + threadIdx.x;
    if (idx >= 2 * SSv * Dv) return;
    int ch = idx >> 20;
    int s = (idx >> 10) & 1023, dcol = idx & 1023;
    int row = g_sids[ch * SSv + s];
    g_w1s[idx] = W1[(size_t)row * Dv + dcol];
    if (dcol == 0) g_b1s[ch * SSv + s] = b1[row];
}
__global__ void gatherT_kernel(const float* __restrict__ W2)
{
    __shared__ float tile[32][33];
    int ch = blockIdx.x / (SSv / 32);
    int s0 = (blockIdx.x % (SSv / 32)) * 32, d0 = blockIdx.y * 32;
    int tx = threadIdx.x & 31, ty8 = threadIdx.x >> 5;
    for (int r = ty8; r < 32; r += 8) {
        int row = g_sids[ch * SSv + s0 + r];
        tile[r][tx] = W2[(size_t)row * Dv + d0 + tx];
    }
    __syncthreads();
    float* dst = g_w2sT + (size_t)ch * Dv * SSv;
    for (int r = ty8; r < 32; r += 8)
        dst[(size_t)(d0 + r) * SSv + s0 + tx] = tile[tx][r];
}
__global__ void tanhpns_kernel()
{
    int idx = blockIdx.x * 256 + threadIdx.x;
    if (idx >= 2 * SSv * LKv) return;
    int ch = idx >> 17;
    int s = (idx >> 7) & 1023, lk = idx & 127;
    int row = g_sids[ch * SSv + s];
    g_tanhpns[idx] = tanhf(g_projn[(size_t)lk * NCv + row]);
}

// ---------------- triplet loss ----------------
__global__ void __launch_bounds__(256)
triplet2()
{
    __shared__ float vals[8][1024];
    int w = threadIdx.x >> 5, lane = threadIdx.x & 31;
    int t = blockIdx.x * 8 + w;
    int ch = t >> 10;
    const float* lrow = g_logits + (size_t)t * SSv;
    const float* tpns = g_tanhpns + (size_t)ch * SSv * LKv;

    float apos = 0.f, aneg = 0.f;
    for (int phase = 0; phase < 2; phase++) {
        for (int i = lane; i < 256; i += 32)
            ((float4*)vals[w])[i] = ((const float4*)lrow)[i];
        __syncwarp();
        float sv[4] = {0.f, 0.f, 0.f, 0.f};
        for (int it = 0; it < PPv; it++) {
            float bv = (phase == 0) ? -1e30f : 1e30f;
            int bi = 1 << 30;
            #pragma unroll
            for (int qd = 0; qd < 32; qd++) {
                int i = lane + (qd << 5);
                float x = vals[w][i];
                bool better = (phase == 0) ? (x > bv) : (x < bv);
                if (better) { bv = x; bi = i; }
            }
            #pragma unroll
            for (int off = 16; off > 0; off >>= 1) {
                float ov = __shfl_xor_sync(0xffffffffu, bv, off);
                int   oi = __shfl_xor_sync(0xffffffffu, bi, off);
                bool take = (phase == 0)
                    ? (ov > bv || (ov == bv && oi < bi))
                    : (ov < bv || (ov == bv && oi < bi));
                if (take) { bv = ov; bi = oi; }
            }
            #pragma unroll
            for (int c2 = 0; c2 < 4; c2++)
                sv[c2] += tpns[(size_t)bi * LKv + lane + 32 * c2];
            if (lane == 0) vals[w][bi] = (phase == 0) ? -1e30f : 1e30f;
            __syncwarp();
        }
        float a = 0.f;
        #pragma unroll
        for (int c2 = 0; c2 < 4; c2++)
            a += sv[c2] * g_tanhpt[(size_t)t * LKv + lane + 32 * c2];
        #pragma unroll
        for (int off = 16; off > 0; off >>= 1)
            a += __shfl_xor_sync(0xffffffffu, a, off);
        a *= 1.0f / (128.0f * 64.0f);
        if (phase == 0) apos = a; else aneg = a;
    }
    if (lane == 0) g_trip[t] = fmaxf(aneg - apos + 0.5f, 0.f);
}

__global__ void trip_reduce(float* __restrict__ outp)
{
    __shared__ float red[1024];
    int tid = threadIdx.x;
    red[tid] = g_trip[tid] + g_trip[tid + 1024];
    __syncthreads();
    for (int st = 512; st > 0; st >>= 1) { if (tid < st) red[tid] += red[tid + st]; __syncthreads(); }
    if (tid == 0) *outp = red[0] * (1.0f / 2048.0f);
}

// ---------------- host ----------------
extern "C" void kernel_launch(void* const* d_in, const int* in_sizes, int n_in,
                              void* d_out, int out_size)
{
    const float* hidden = (const float*)d_in[0];
    const float* amask  = (const float*)d_in[1];
    const float* ln1_g  = (const float*)d_in[2];
    const float* ln1_b  = (const float*)d_in[3];
    const float* Wq     = (const float*)d_in[4];
    const float* bq     = (const float*)d_in[5];
    const float* Wk     = (const float*)d_in[6];
    const float* bk     = (const float*)d_in[7];
    const float* Wv     = (const float*)d_in[8];
    const float* bv     = (const float*)d_in[9];
    const float* Wo     = (const float*)d_in[10];
    const float* bo     = (const float*)d_in[11];
    const float* ln2_g  = (const float*)d_in[12];
    const float* ln2_b  = (const float*)d_in[13];
    const float* W1     = (const float*)d_in[14];
    const float* b1     = (const float*)d_in[15];
    const float* Whash  = (const float*)d_in[16];
    const float* W2     = (const float*)d_in[17];
    const float* b2     = (const float*)d_in[18];
    float* out = (float*)d_out;

    float *xln, *ctx, *attn, *normed;
    float *w1s, *w2sT, *b1s, *logits, *acts;
    unsigned *qh, *ql, *kh, *kl, *vh, *vl;
    int* histp;
    cudaGetSymbolAddress((void**)&xln,    g_xln);
    cudaGetSymbolAddress((void**)&qh,     g_qh);
    cudaGetSymbolAddress((void**)&ql,     g_ql);
    cudaGetSymbolAddress((void**)&kh,     g_kh);
    cudaGetSymbolAddress((void**)&kl,     g_kl);
    cudaGetSymbolAddress((void**)&vh,     g_vh);
    cudaGetSymbolAddress((void**)&vl,     g_vl);
    cudaGetSymbolAddress((void**)&ctx,    g_ctx);
    cudaGetSymbolAddress((void**)&attn,   g_attn);
    cudaGetSymbolAddress((void**)&normed, g_normed);
    cudaGetSymbolAddress((void**)&w1s,    g_w1s);
    cudaGetSymbolAddress((void**)&w2sT,   g_w2sT);
    cudaGetSymbolAddress((void**)&b1s,    g_b1s);
    cudaGetSymbolAddress((void**)&logits, g_logits);
    cudaGetSymbolAddress((void**)&acts,   g_acts);
    cudaGetSymbolAddress((void**)&histp,  g_hist);

    const int SM3  = (128 + 128) * 36 * 4 * 2;   // 73728
    const int SM1B = (128 + 128) * 36 * 4;       // 36864
    const int SMAT = (4*64*LDQ + 2*64*LDVt) * 4 + 64*4;
    cudaFuncSetAttribute((const void*)mma_nt<3,2,true,false,128,128,false,0>,
                         cudaFuncAttributeMaxDynamicSharedMemorySize, SM3);
    cudaFuncSetAttribute((const void*)mma_nt<3,0,true,true,128,128,false,0>,
                         cudaFuncAttributeMaxDynamicSharedMemorySize, SM3);
    cudaFuncSetAttribute((const void*)mma_nt<1,1,true,false,128,128,true,SSv>,
                         cudaFuncAttributeMaxDynamicSharedMemorySize, SM1B);
    cudaFuncSetAttribute((const void*)mma_nt<1,0,true,true,128,128,true,0>,
                         cudaFuncAttributeMaxDynamicSharedMemorySize, SM1B);
    cudaFuncSetAttribute((const void*)attn4,
                         cudaFuncAttributeMaxDynamicSharedMemorySize, SMAT);

    // ---- attention path ----
    ln_kernel<<<SQv, 256>>>(hidden, ln1_g, ln1_b, xln);
    msk_kernel<<<SQv/256, 256>>>(amask);
    dim3 gA(Dv/128, SQv/128);
    mma_nt<3,2,true,false,128,128,false,0><<<gA, 256, SM3>>>(xln, Wq, bq, nullptr,
                                                             (float*)qh, (float*)ql, SQv, Dv, Dv);
    mma_nt<3,2,true,false,128,128,false,0><<<gA, 256, SM3>>>(xln, Wk, bk, nullptr,
                                                             (float*)kh, (float*)kl, SQv, Dv, Dv);
    mma_nt<3,2,true,false,128,128,false,0><<<gA, 256, SM3>>>(xln, Wv, bv, nullptr,
                                                             (float*)vh, (float*)vl, SQv, Dv, Dv);
    attn4<<<dim3(SQv/64, Hv), 128, SMAT>>>(qh, ql, kh, kl, vh, vl, ctx);
    mma_nt<3,0,true,true,128,128,false,0><<<gA, 256, SM3>>>(ctx, Wo, bo, hidden,
                                                            attn, nullptr, SQv, Dv, Dv);

    // ---- FFN prep ----
    ln_kernel<<<SQv, 256>>>(attn, ln2_g, ln2_b, normed);
    // merged hash GEMM: projn (64 x-blocks) + projt w/ fused tanh-transpose (32 x-blocks)
    gemm_hash<<<dim3(NCv/64 + NTOK/64, LKv/64), 256>>>(Whash, W1, normed);
    coden_kernel<<<(LTv * NCv) / 256, 256>>>();

    // ---- LSH FFN (chunks fused) ----
    cudaMemsetAsync(histp, 0, 2 * LTv * NBv * sizeof(int), 0);
    codet_hist_kernel<<<(LTv * NTOK) / 256, 256>>>();
    score_kernel<<<(2 * NCv) / 256, 256>>>();
    select_kernel<<<2, 1024>>>();
    gather_kernel<<<(2 * SSv * Dv) / 256, 256>>>(W1, b1);
    gatherT_kernel<<<dim3(2 * SSv / 32, Dv / 32), 256>>>(W2);
    tanhpns_kernel<<<(2 * SSv * LKv) / 256, 256>>>();

    // logits + fused GELU (both chunks, BM=128 tile, one launch via CHSEL)
    mma_nt<1,1,true,false,128,128,true,SSv><<<dim3(SSv/128, NTOK/128), 256, SM1B>>>(
        normed, w1s, b1s, nullptr, logits, acts, NTOK, SSv, Dv);
    triplet2<<<NTOK/8, 256>>>();
    // out = acts @ W2s^T + b2 + attn residual (both chunks, BM=128 tile)
    mma_nt<1,0,true,true,128,128,true,0><<<dim3(Dv/128, NTOK/128), 256, SM1B>>>(
        acts, w2sT, b2, attn, out, nullptr, NTOK, Dv, SSv);

    // ---- scalar output ----
    trip_reduce<<<1, 1024>>>(out + (size_t)SQv * Dv);
}